// round 2
// baseline (speedup 1.0000x reference)
#include <cuda_runtime.h>
#include <math.h>

#define HW 65536            // 256*256
#define NCH 16

// ---------------- device scratch (allocation-free) ----------------
__device__ float g_bufA[2*16*8*HW];          // 64 MB ping
__device__ float g_bufB[2*16*8*HW];          // 64 MB pong
__device__ float g_wrL[8*3*16*49];           // rotated lift weights [m][ci][co][49]
__device__ float g_krot[8*128*16*25];        // rotated gconv weights [m][ci*8+o][co][25]
__device__ float g_w4[128*128];              // orientation-shifted 1x1 weights [p=co*8+m][q=ci*8+o]
__device__ float g_psum[16*64];
__device__ float g_psq[16*64];
__device__ float g_sc[16];
__device__ float g_bi[16];

// ---------------- bilinear kernel rotation ----------------
__device__ __forceinline__ float rot_sample(const float* W, int k, float cs, float sn,
                                            int i, int j) {
    float c  = 0.5f * (float)(k - 1);
    float ys = (float)i - c, xs = (float)j - c;
    float sy = cs * ys - sn * xs + c;
    float sx = sn * ys + cs * xs + c;
    float fy = floorf(sy), fx = floorf(sx);
    int y0 = (int)fy, x0 = (int)fx;
    float wy = sy - fy, wx = sx - fx;
    float v00 = (y0   >= 0 && y0   < k && x0   >= 0 && x0   < k) ? W[y0*k + x0]       : 0.f;
    float v01 = (y0   >= 0 && y0   < k && x0+1 >= 0 && x0+1 < k) ? W[y0*k + x0 + 1]   : 0.f;
    float v10 = (y0+1 >= 0 && y0+1 < k && x0   >= 0 && x0   < k) ? W[(y0+1)*k + x0]   : 0.f;
    float v11 = (y0+1 >= 0 && y0+1 < k && x0+1 >= 0 && x0+1 < k) ? W[(y0+1)*k + x0+1] : 0.f;
    return v00*(1.f-wy)*(1.f-wx) + v01*(1.f-wy)*wx + v10*wy*(1.f-wx) + v11*wy*wx;
}

__global__ void rotate_lift_kernel(const float* __restrict__ lw) {
    int idx = blockIdx.x * 256 + threadIdx.x;
    if (idx >= 8*3*16*49) return;
    int j  = idx % 49;
    int co = (idx / 49) % 16;
    int ci = (idx / (49*16)) % 3;
    int m  = idx / (49*48);
    float th = (float)((double)m * (2.0 * M_PI / 8.0));
    float cs = cosf(th), sn = sinf(th);
    const float* W = lw + (co*3 + ci) * 49;
    g_wrL[((m*3 + ci)*16 + co)*49 + j] = rot_sample(W, 7, cs, sn, j/7, j%7);
}

__global__ void rotate_g_kernel(const float* __restrict__ w) {
    int idx = blockIdx.x * 256 + threadIdx.x;   // grid sized to exactly 409600
    int j    = idx % 25;
    int co   = (idx / 25) % 16;
    int c128 = (idx / 400) % 128;
    int m    = idx / (400*128);
    int ci = c128 >> 3, o = c128 & 7;
    int oo = (o + 8 - m) & 7;                   // (o - m) mod 8
    float th = (float)((double)m * (2.0 * M_PI / 8.0));
    float cs = cosf(th), sn = sinf(th);
    const float* W = w + ((co*16 + ci)*8 + oo) * 25;
    g_krot[idx] = rot_sample(W, 5, cs, sn, j/5, j%5);
}

__global__ void build_w4_kernel(const float* __restrict__ w4) {
    int idx = blockIdx.x * 256 + threadIdx.x;   // 16384
    int q = idx & 127, p = idx >> 7;
    int co = p >> 3, m = p & 7;
    int ci = q >> 3, o = q & 7;
    g_w4[idx] = w4[(co*16 + ci)*8 + ((o + 8 - m) & 7)];
}

// ---------------- lift conv: x[2,3,256,256] (reflect pad 3, 7x7) -> g_bufA[2,16,8,256,256]
__global__ __launch_bounds__(256) void lift_kernel(const float* __restrict__ x) {
    int z = blockIdx.z; int b = z >> 3, m = z & 7;
    int x0 = blockIdx.x * 16, y0 = blockIdx.y * 16;
    int t = threadIdx.x; int tx = t & 15, ty = t >> 4;
    __shared__ float s_in[22*22];
    __shared__ float s_w[16*49];
    float acc[16];
#pragma unroll
    for (int i = 0; i < 16; ++i) acc[i] = 0.f;
#pragma unroll 1
    for (int ci = 0; ci < 3; ++ci) {
        const float* ip = x + (b*3 + ci) * HW;
        for (int idx = t; idx < 484; idx += 256) {
            int iy = idx / 22, ix = idx - iy*22;
            int gy = y0 + iy - 3; gy = gy < 0 ? -gy : (gy > 255 ? 510 - gy : gy);
            int gx = x0 + ix - 3; gx = gx < 0 ? -gx : (gx > 255 ? 510 - gx : gx);
            s_in[idx] = ip[gy*256 + gx];
        }
        const float* wp = g_wrL + (m*3 + ci) * 16 * 49;
        for (int idx = t; idx < 784; idx += 256) s_w[idx] = wp[idx];
        __syncthreads();
        float tap[49];
#pragma unroll
        for (int ky = 0; ky < 7; ++ky)
#pragma unroll
            for (int kx = 0; kx < 7; ++kx)
                tap[ky*7 + kx] = s_in[(ty+ky)*22 + tx + kx];
#pragma unroll
        for (int co = 0; co < 16; ++co) {
            float a = acc[co];
#pragma unroll
            for (int j = 0; j < 49; ++j)
                a = fmaf(tap[j], s_w[co*49 + j], a);
            acc[co] = a;
        }
        __syncthreads();
    }
    int pix = (y0 + ty) * 256 + x0 + tx;
#pragma unroll
    for (int co = 0; co < 16; ++co)
        g_bufA[((b*16 + co)*8 + m)*HW + pix] = acc[co];
}

// ---------------- BN stats: deterministic two-level reduction ----------------
__global__ void stats_partial_kernel(int which) {
    const float* in = which ? g_bufB : g_bufA;
    int c = blockIdx.y, chunk = blockIdx.x, t = threadIdx.x;
    float s = 0.f, ss = 0.f;
    int base = chunk * 16384 + t;
#pragma unroll 4
    for (int k = 0; k < 64; ++k) {
        int e = base + k * 256;
        int b = e >> 19;
        int r = e & ((1 << 19) - 1);
        float v = in[((b*16 + c) << 19) + r];
        s += v; ss += v * v;
    }
    __shared__ float sh1[256], sh2[256];
    sh1[t] = s; sh2[t] = ss;
    __syncthreads();
    for (int off = 128; off > 0; off >>= 1) {
        if (t < off) { sh1[t] += sh1[t + off]; sh2[t] += sh2[t + off]; }
        __syncthreads();
    }
    if (t == 0) { g_psum[c*64 + chunk] = sh1[0]; g_psq[c*64 + chunk] = sh2[0]; }
}

__global__ void stats_final_kernel(const float* __restrict__ g, const float* __restrict__ b) {
    int c = threadIdx.x;
    if (c >= 16) return;
    float s = 0.f, ss = 0.f;
    for (int i = 0; i < 64; ++i) { s += g_psum[c*64 + i]; ss += g_psq[c*64 + i]; }
    const float invN = 1.0f / 1048576.0f;
    float mean = s * invN;
    float var  = ss * invN - mean * mean;
    float sc = g[c] * rsqrtf(var + 1e-5f);
    g_sc[c] = sc;
    g_bi[c] = b[c] - mean * sc;
}

// ---------------- g-conv 5x5 (reflect pad 2), input fused BN+ReLU ----------------
// Each thread: 2x2 pixels x 8 output channels. Block tile 32x32 pixels.
// dir=0: A->B, dir=1: B->A
__global__ __launch_bounds__(256, 2) void gconv_kernel(int dir) {
    const float* in = dir ? g_bufB : g_bufA;
    float* out      = dir ? g_bufA : g_bufB;
    int bz = blockIdx.z;
    int ch = bz & 1;
    int m  = (bz >> 1) & 7;
    int b  = bz >> 4;
    int x0 = blockIdx.x * 32, y0 = blockIdx.y * 32;
    int t = threadIdx.x;
    int lx = (t & 15) * 2, ly = (t >> 4) * 2;
    __shared__ float s_in[36*36];
    __shared__ float s_w[200];
    float acc[8][4];
#pragma unroll
    for (int i = 0; i < 8; ++i) { acc[i][0]=acc[i][1]=acc[i][2]=acc[i][3]=0.f; }
    const float* wbase = g_krot + (size_t)m * 51200 + ch * 200;
#pragma unroll 1
    for (int c128 = 0; c128 < 128; ++c128) {
        int ci = c128 >> 3;
        const float* ip = in + ((b*16 + ci)*8 + (c128 & 7)) * HW;
        float sc = g_sc[ci], bi = g_bi[ci];
        for (int idx = t; idx < 1296; idx += 256) {
            int iy = idx / 36, ix = idx - iy*36;
            int gy = y0 + iy - 2; gy = gy < 0 ? -gy : (gy > 255 ? 510 - gy : gy);
            int gx = x0 + ix - 2; gx = gx < 0 ? -gx : (gx > 255 ? 510 - gx : gx);
            s_in[idx] = fmaxf(fmaf(ip[gy*256 + gx], sc, bi), 0.f);
        }
        if (t < 200) s_w[t] = wbase[c128 * 400 + t];
        __syncthreads();
        float tap[36];
#pragma unroll
        for (int r = 0; r < 6; ++r)
#pragma unroll
            for (int cc = 0; cc < 6; ++cc)
                tap[r*6 + cc] = s_in[(ly + r)*36 + lx + cc];
#pragma unroll
        for (int co = 0; co < 8; ++co) {
#pragma unroll
            for (int ky = 0; ky < 5; ++ky)
#pragma unroll
                for (int kx = 0; kx < 5; ++kx) {
                    float w = s_w[co*25 + ky*5 + kx];
                    acc[co][0] = fmaf(tap[ky*6 + kx],       w, acc[co][0]);
                    acc[co][1] = fmaf(tap[ky*6 + kx + 1],   w, acc[co][1]);
                    acc[co][2] = fmaf(tap[(ky+1)*6 + kx],   w, acc[co][2]);
                    acc[co][3] = fmaf(tap[(ky+1)*6 + kx+1], w, acc[co][3]);
                }
        }
        __syncthreads();
    }
#pragma unroll
    for (int j = 0; j < 8; ++j) {
        int co = ch*8 + j;
        float* op = out + ((b*16 + co)*8 + m) * HW;
        *(float2*)&op[(y0+ly  )*256 + x0 + lx] = make_float2(acc[j][0], acc[j][1]);
        *(float2*)&op[(y0+ly+1)*256 + x0 + lx] = make_float2(acc[j][2], acc[j][3]);
    }
}

// ---------------- conv4: 1x1 orientation-mixing conv (B -> A), fused input BN+ReLU
__global__ __launch_bounds__(256) void conv4_kernel() {
    const float* in = g_bufB;
    float* out = g_bufA;
    int b = blockIdx.y;
    int pix0 = blockIdx.x * 64;
    int t = threadIdx.x;
    int pix = t & 63, pg = t >> 6;
    __shared__ float s_x[512];
    __shared__ float s_w[1024];
    float acc[32];
#pragma unroll
    for (int j = 0; j < 32; ++j) acc[j] = 0.f;
#pragma unroll 1
    for (int qb = 0; qb < 16; ++qb) {
        for (int idx = t; idx < 512; idx += 256) {
            int q8 = idx >> 6, p = idx & 63;
            int q = qb*8 + q8;
            float v = in[(b*128 + q)*HW + pix0 + p];
            s_x[idx] = fmaxf(fmaf(v, g_sc[q >> 3], g_bi[q >> 3]), 0.f);
        }
        for (int idx = t; idx < 1024; idx += 256) {
            int po = idx >> 3, q8 = idx & 7;
            s_w[idx] = g_w4[po*128 + qb*8 + q8];
        }
        __syncthreads();
#pragma unroll
        for (int q8 = 0; q8 < 8; ++q8) {
            float xv = s_x[q8*64 + pix];
#pragma unroll
            for (int j = 0; j < 32; ++j)
                acc[j] = fmaf(xv, s_w[(pg*32 + j)*8 + q8], acc[j]);
        }
        __syncthreads();
    }
#pragma unroll
    for (int j = 0; j < 32; ++j)
        out[(b*128 + pg*32 + j)*HW + pix0 + pix] = acc[j];
}

// ---------------- final: BN4+ReLU, max over orientation, 1x1 + sigmoid ----------------
__global__ void final_kernel(const float* __restrict__ fw, float* __restrict__ out) {
    int gid = blockIdx.x * 256 + threadIdx.x;   // 131072 total
    int b = gid >> 16, pix = gid & 65535;
    float acc = 0.f;
#pragma unroll 1
    for (int co = 0; co < 16; ++co) {
        float sc = g_sc[co], bi = g_bi[co];
        float mv = 0.f;   // relu(v) >= 0, so max over relu == max(0, max v)
#pragma unroll
        for (int m = 0; m < 8; ++m) {
            float v = fmaf(g_bufA[((b*16 + co)*8 + m)*HW + pix], sc, bi);
            mv = fmaxf(mv, v);
        }
        acc = fmaf(fw[co], mv, acc);
    }
    out[gid] = 1.0f / (1.0f + expf(-acc));
}

// ---------------- launch ----------------
extern "C" void kernel_launch(void* const* d_in, const int* in_sizes, int n_in,
                              void* d_out, int out_size) {
    const float* x  = (const float*)d_in[0];
    const float* lw = (const float*)d_in[1];
    const float* w1 = (const float*)d_in[2];
    const float* w2 = (const float*)d_in[3];
    const float* w3 = (const float*)d_in[4];
    const float* w4 = (const float*)d_in[5];
    const float* fw = (const float*)d_in[6];
    const float* g0 = (const float*)d_in[7];  const float* b0 = (const float*)d_in[8];
    const float* g1 = (const float*)d_in[9];  const float* b1 = (const float*)d_in[10];
    const float* g2 = (const float*)d_in[11]; const float* b2 = (const float*)d_in[12];
    const float* g3 = (const float*)d_in[13]; const float* b3 = (const float*)d_in[14];
    const float* g4 = (const float*)d_in[15]; const float* b4 = (const float*)d_in[16];
    float* out = (float*)d_out;

    // lift + BN0 stats
    rotate_lift_kernel<<<74, 256>>>(lw);
    lift_kernel<<<dim3(16,16,16), 256>>>(x);
    stats_partial_kernel<<<dim3(64,16), 256>>>(0);
    stats_final_kernel<<<1, 16>>>(g0, b0);

    // gconv1 (A->B) + BN1 stats
    rotate_g_kernel<<<1600, 256>>>(w1);
    gconv_kernel<<<dim3(8,8,32), 256>>>(0);
    stats_partial_kernel<<<dim3(64,16), 256>>>(1);
    stats_final_kernel<<<1, 16>>>(g1, b1);

    // gconv2 (B->A) + BN2 stats
    rotate_g_kernel<<<1600, 256>>>(w2);
    gconv_kernel<<<dim3(8,8,32), 256>>>(1);
    stats_partial_kernel<<<dim3(64,16), 256>>>(0);
    stats_final_kernel<<<1, 16>>>(g2, b2);

    // gconv3 (A->B) + BN3 stats
    rotate_g_kernel<<<1600, 256>>>(w3);
    gconv_kernel<<<dim3(8,8,32), 256>>>(0);
    stats_partial_kernel<<<dim3(64,16), 256>>>(1);
    stats_final_kernel<<<1, 16>>>(g3, b3);

    // conv4 (B->A) + BN4 stats
    build_w4_kernel<<<64, 256>>>(w4);
    conv4_kernel<<<dim3(1024,2), 256>>>();
    stats_partial_kernel<<<dim3(64,16), 256>>>(0);
    stats_final_kernel<<<1, 16>>>(g4, b4);

    // max-project + final 1x1 + sigmoid
    final_kernel<<<512, 256>>>(fw, out);
}

// round 5
// speedup vs baseline: 8.4638x; 8.4638x over previous
#include <cuda_runtime.h>
#include <cuda_fp16.h>
#include <math.h>
#include <stdint.h>

#define HW 65536
#define PW 260

// ---------------- device scratch (allocation-free) ----------------
__device__ float  g_raw[2*128*HW];                       // conv outputs fp32 [b][p][y][x]
__device__ __align__(1024) __half g_act[2*PW*PW*128];    // padded NHWC fp16 activations
__device__ __align__(1024) __half g_wA[25*16384];        // gconv weights [tap][p][q] fp16
__device__ __align__(1024) __half g_wA4[16384];          // conv4 weights [p][q] fp16
__device__ float g_wrL[8*3*16*49];
__device__ float g_psum[16*64], g_psq[16*64];
__device__ float g_ps1[1024*128], g_ps2[1024*128];       // per-tile per-p partials
__device__ float g_sc[16], g_bi[16];

// ---------------- PTX helpers (sm_80-era only: portable to plain sm_103) ----------------
__device__ __forceinline__ uint32_t smem_u32(const void* p) {
    uint32_t a;
    asm("{ .reg .u64 t; cvta.to.shared.u64 t, %1; cvt.u32.u64 %0, t; }" : "=r"(a) : "l"(p));
    return a;
}
__device__ __forceinline__ void cp_async16(uint32_t s, const void* g) {
    asm volatile("cp.async.cg.shared.global [%0], [%1], 16;" :: "r"(s), "l"(g) : "memory");
}
__device__ __forceinline__ void ldm_x4(uint32_t* r, uint32_t a) {
    asm volatile("ldmatrix.sync.aligned.m8n8.x4.shared.b16 {%0,%1,%2,%3}, [%4];"
        : "=r"(r[0]), "=r"(r[1]), "=r"(r[2]), "=r"(r[3]) : "r"(a));
}
__device__ __forceinline__ void mma16816(float* d, const uint32_t* a, const uint32_t* b) {
    asm volatile("mma.sync.aligned.m16n8k16.row.col.f32.f16.f16.f32 "
        "{%0,%1,%2,%3}, {%4,%5,%6,%7}, {%8,%9}, {%0,%1,%2,%3};"
        : "+f"(d[0]), "+f"(d[1]), "+f"(d[2]), "+f"(d[3])
        : "r"(a[0]), "r"(a[1]), "r"(a[2]), "r"(a[3]), "r"(b[0]), "r"(b[1]));
}

// ---------------- bilinear kernel rotation ----------------
__device__ __forceinline__ float rot_sample(const float* W, int k, float cs, float sn, int i, int j) {
    float c  = 0.5f * (float)(k - 1);
    float ys = (float)i - c, xs = (float)j - c;
    float sy = cs * ys - sn * xs + c;
    float sx = sn * ys + cs * xs + c;
    float fy = floorf(sy), fx = floorf(sx);
    int y0 = (int)fy, x0 = (int)fx;
    float wy = sy - fy, wx = sx - fx;
    float v00 = (y0   >= 0 && y0   < k && x0   >= 0 && x0   < k) ? W[y0*k + x0]       : 0.f;
    float v01 = (y0   >= 0 && y0   < k && x0+1 >= 0 && x0+1 < k) ? W[y0*k + x0 + 1]   : 0.f;
    float v10 = (y0+1 >= 0 && y0+1 < k && x0   >= 0 && x0   < k) ? W[(y0+1)*k + x0]   : 0.f;
    float v11 = (y0+1 >= 0 && y0+1 < k && x0+1 >= 0 && x0+1 < k) ? W[(y0+1)*k + x0+1] : 0.f;
    return v00*(1.f-wy)*(1.f-wx) + v01*(1.f-wy)*wx + v10*wy*(1.f-wx) + v11*wy*wx;
}

__global__ void rotate_lift_kernel(const float* __restrict__ lw) {
    int idx = blockIdx.x * 256 + threadIdx.x;
    if (idx >= 8*3*16*49) return;
    int j  = idx % 49;
    int co = (idx / 49) % 16;
    int ci = (idx / (49*16)) % 3;
    int m  = idx / (49*48);
    float th = (float)m * 0.78539816339744831f;
    float cs = cosf(th), sn = sinf(th);
    const float* W = lw + (co*3 + ci) * 49;
    g_wrL[((m*3 + ci)*16 + co)*49 + j] = rot_sample(W, 7, cs, sn, j/7, j%7);
}

// pack gconv weights: g_wA[tap][p=co*8+m][q=ci*8+o]
__global__ void pack_g_kernel(const float* __restrict__ w) {
    int idx = blockIdx.x * 256 + threadIdx.x;   // 409600 exact
    int tap = idx >> 14;
    int p = (idx >> 7) & 127, q = idx & 127;
    int co = p >> 3, m = p & 7, ci = q >> 3, o = q & 7;
    int oo = (o - m) & 7;
    float th = (float)m * 0.78539816339744831f;
    float cs = cosf(th), sn = sinf(th);
    float v = rot_sample(w + ((co*16 + ci)*8 + oo)*25, 5, cs, sn, tap/5, tap%5);
    g_wA[tap*16384 + p*128 + q] = __float2half(v);
}

__global__ void pack_w4_kernel(const float* __restrict__ w4) {
    int idx = blockIdx.x * 256 + threadIdx.x;   // 16384
    int p = idx >> 7, q = idx & 127;
    int co = p >> 3, m = p & 7, ci = q >> 3, o = q & 7;
    g_wA4[idx] = __float2half(w4[(co*16 + ci)*8 + ((o - m) & 7)]);
}

// ---------------- lift conv (scalar fp32) -> g_raw ----------------
__global__ __launch_bounds__(256) void lift_kernel(const float* __restrict__ x) {
    int z = blockIdx.z; int b = z >> 3, m = z & 7;
    int x0 = blockIdx.x * 16, y0 = blockIdx.y * 16;
    int t = threadIdx.x; int tx = t & 15, ty = t >> 4;
    __shared__ float s_in[22*22];
    __shared__ float s_w[16*49];
    float acc[16];
#pragma unroll
    for (int i = 0; i < 16; ++i) acc[i] = 0.f;
#pragma unroll 1
    for (int ci = 0; ci < 3; ++ci) {
        const float* ip = x + (b*3 + ci) * HW;
        for (int idx = t; idx < 484; idx += 256) {
            int iy = idx / 22, ix = idx - iy*22;
            int gy = y0 + iy - 3; gy = gy < 0 ? -gy : (gy > 255 ? 510 - gy : gy);
            int gx = x0 + ix - 3; gx = gx < 0 ? -gx : (gx > 255 ? 510 - gx : gx);
            s_in[idx] = ip[gy*256 + gx];
        }
        const float* wp = g_wrL + (m*3 + ci) * 784;
        for (int idx = t; idx < 784; idx += 256) s_w[idx] = wp[idx];
        __syncthreads();
        float tap[49];
#pragma unroll
        for (int ky = 0; ky < 7; ++ky)
#pragma unroll
            for (int kx = 0; kx < 7; ++kx)
                tap[ky*7 + kx] = s_in[(ty+ky)*22 + tx + kx];
#pragma unroll
        for (int co = 0; co < 16; ++co) {
            float a = acc[co];
#pragma unroll
            for (int j = 0; j < 49; ++j) a = fmaf(tap[j], s_w[co*49 + j], a);
            acc[co] = a;
        }
        __syncthreads();
    }
    int pix = (y0 + ty) * 256 + x0 + tx;
#pragma unroll
    for (int co = 0; co < 16; ++co)
        g_raw[((b*16 + co)*8 + m)*HW + pix] = acc[co];
}

// ---------------- BN0 stats ----------------
__global__ void stats_partial_kernel() {
    int c = blockIdx.y, chunk = blockIdx.x, t = threadIdx.x;
    float s = 0.f, ss = 0.f;
    int base = chunk * 16384 + t;
#pragma unroll 4
    for (int k = 0; k < 64; ++k) {
        int e = base + k * 256;
        int b = e >> 19;
        int r = e & ((1 << 19) - 1);
        float v = g_raw[((b*16 + c) << 19) + r];
        s += v; ss += v * v;
    }
    __shared__ float sh1[256], sh2[256];
    sh1[t] = s; sh2[t] = ss;
    __syncthreads();
    for (int off = 128; off > 0; off >>= 1) {
        if (t < off) { sh1[t] += sh1[t + off]; sh2[t] += sh2[t + off]; }
        __syncthreads();
    }
    if (t == 0) { g_psum[c*64 + chunk] = sh1[0]; g_psq[c*64 + chunk] = sh2[0]; }
}

__global__ void stats_final_kernel(const float* __restrict__ g, const float* __restrict__ b) {
    int c = threadIdx.x;
    if (c >= 16) return;
    float s = 0.f, ss = 0.f;
    for (int i = 0; i < 64; ++i) { s += g_psum[c*64 + i]; ss += g_psq[c*64 + i]; }
    const float invN = 1.0f / 1048576.0f;
    float mean = s * invN;
    float var  = ss * invN - mean * mean;
    float sc = g[c] * rsqrtf(var + 1e-5f);
    g_sc[c] = sc;
    g_bi[c] = b[c] - mean * sc;
}

// BN stats from MMA epilogue partials (1024 tiles x 128 p)
__global__ void stats_final_mma(const float* __restrict__ g, const float* __restrict__ b) {
    int c = blockIdx.x, t = threadIdx.x;
    float s = 0.f, ss = 0.f;
    for (int e = t; e < 8192; e += 256) {
        int idx = (e >> 3) * 128 + c*8 + (e & 7);
        s += g_ps1[idx]; ss += g_ps2[idx];
    }
    __shared__ float sh1[256], sh2[256];
    sh1[t] = s; sh2[t] = ss;
    __syncthreads();
    for (int off = 128; off > 0; off >>= 1) {
        if (t < off) { sh1[t] += sh1[t + off]; sh2[t] += sh2[t + off]; }
        __syncthreads();
    }
    if (t == 0) {
        const float invN = 1.0f / 1048576.0f;
        float mean = sh1[0] * invN;
        float var  = sh2[0] * invN - mean * mean;
        float sc = g[c] * rsqrtf(var + 1e-5f);
        g_sc[c] = sc;
        g_bi[c] = b[c] - mean * sc;
    }
}

// ---------------- BN+ReLU+pad+fp16 convert via SMEM transpose: g_raw -> g_act ----------------
__global__ __launch_bounds__(256) void convert_kernel() {
    __shared__ __half s[128][33];
    int t = threadIdx.x;
    int py = blockIdx.y, b = blockIdx.z;
    int pxb = blockIdx.x * 32;
    int sy = py - 2; sy = sy < 0 ? -sy : (sy > 255 ? 510 - sy : sy);
    int lanepx = t & 31, wch = t >> 5;
    {
        int pg = pxb + lanepx;
        int sx = pg - 2; sx = sx < 0 ? -sx : (sx > 255 ? 510 - sx : sx);
        bool ok = pg < PW;
        const float* rp = g_raw + (size_t)b*128*HW + sy*256 + sx;
#pragma unroll
        for (int i = 0; i < 16; ++i) {
            int ch = wch + i*8;
            float f = ok ? rp[(size_t)ch * HW] : 0.f;
            f = fmaxf(fmaf(f, g_sc[ch >> 3], g_bi[ch >> 3]), 0.f);
            s[ch][lanepx] = __float2half(f);
        }
    }
    __syncthreads();
#pragma unroll
    for (int i = 0; i < 2; ++i) {
        int idx = i*256 + t;            // 512 = 32 px x 16 chunks
        int px = idx >> 4, qc = idx & 15;
        int pg = pxb + px;
        if (pg >= PW) continue;
        __half h[8];
#pragma unroll
        for (int k = 0; k < 8; ++k) h[k] = s[qc*8 + k][px];
        *(uint4*)(g_act + ((size_t)(b*PW + py)*PW + pg)*128 + qc*8) = *(uint4*)h;
    }
}

// ---------------- mma.sync implicit-GEMM conv: g_act -> g_raw + stats partials ----------------
// CTA tile: 128 p x 128 px, K=128/tap. 8 warps: mw = w&3 (32 p), nw = w>>2 (64 px).
// SMEM stage: A 32KB + B 32KB, double buffered (cp.async).
__global__ __launch_bounds__(256, 1) void mma_conv_kernel(int is1x1) {
    extern __shared__ __align__(256) char dsm[];
    uint32_t sbase = smem_u32(dsm);
    float* s_sum = (float*)(dsm + 131072);
    float* s_sq  = (float*)(dsm + 131584);

    int tid = threadIdx.x, w = tid >> 5, lane = tid & 31;
    int mw = w & 3, nw = w >> 2;
    int tile = blockIdx.x;
    int b = tile >> 9, rem = tile & 511;
    int y = rem >> 1, x0 = (rem & 1) << 7;
    int ntap = is1x1 ? 1 : 25;
    const __half* wsrc = is1x1 ? g_wA4 : g_wA;
    const __half* actb = g_act + (size_t)b * PW * PW * 128;

    float d[2][8][4];
#pragma unroll
    for (int mi = 0; mi < 2; ++mi)
#pragma unroll
        for (int nn = 0; nn < 8; ++nn)
#pragma unroll
            for (int k = 0; k < 4; ++k) d[mi][nn][k] = 0.f;

    auto load_tap = [&](int tp, int stg) {
        int ky = is1x1 ? 2 : tp / 5, kx = is1x1 ? 2 : tp % 5;
        const __half* bsrc = actb + ((size_t)(y + ky) * PW + x0 + kx) * 128;
        const __half* asrc = wsrc + tp * 16384;
        uint32_t Ab = sbase + stg * 65536;
        uint32_t Bb = Ab + 32768;
#pragma unroll
        for (int it = 0; it < 8; ++it) {
            int id = it * 256 + tid;
            int r = id >> 4, c = id & 15;
            uint32_t sw = (uint32_t)((c ^ (r & 7)) * 16);
            cp_async16(Ab + r*256 + sw, asrc + id*8);
            cp_async16(Bb + r*256 + sw, bsrc + id*8);
        }
        asm volatile("cp.async.commit_group;" ::: "memory");
    };

    load_tap(0, 0);
#pragma unroll 1
    for (int t = 0; t < ntap; ++t) {
        if (t + 1 < ntap) load_tap(t + 1, (t + 1) & 1);
        if (t + 1 < ntap) { asm volatile("cp.async.wait_group 1;" ::: "memory"); }
        else              { asm volatile("cp.async.wait_group 0;" ::: "memory"); }
        __syncthreads();
        uint32_t Ab = sbase + (t & 1) * 65536;
        uint32_t Bb = Ab + 32768;
        int ar = mw*32 + (lane & 15);           // A row base (+ mi*16)
        int acsel = lane >> 4;                   // A chunk half
        int brb = nw*64 + (lane & 7) + ((lane >> 4) << 3);  // B row base (+ nj*16)
        int bcsel = (lane >> 3) & 1;             // B chunk half
#pragma unroll
        for (int ks = 0; ks < 8; ++ks) {
            uint32_t a[2][4];
#pragma unroll
            for (int mi = 0; mi < 2; ++mi) {
                int r = ar + mi*16;
                int c = ks*2 + acsel;
                ldm_x4(a[mi], Ab + r*256 + ((c ^ (r & 7)) * 16));
            }
            uint32_t bf[8][2];
#pragma unroll
            for (int nj = 0; nj < 4; ++nj) {
                int r = brb + nj*16;
                int c = ks*2 + bcsel;
                uint32_t q[4];
                ldm_x4(q, Bb + r*256 + ((c ^ (r & 7)) * 16));
                bf[nj*2][0]   = q[0]; bf[nj*2][1]   = q[1];
                bf[nj*2+1][0] = q[2]; bf[nj*2+1][1] = q[3];
            }
#pragma unroll
            for (int mi = 0; mi < 2; ++mi)
#pragma unroll
                for (int nn = 0; nn < 8; ++nn)
                    mma16816(d[mi][nn], a[mi], bf[nn]);
        }
        __syncthreads();
    }

    // epilogue: write g_raw + deterministic per-p sums
    int g = lane >> 2, q4 = lane & 3;
    float psum[4], psq[4];
#pragma unroll
    for (int i = 0; i < 4; ++i) { psum[i] = 0.f; psq[i] = 0.f; }
#pragma unroll
    for (int mi = 0; mi < 2; ++mi) {
#pragma unroll
        for (int hh = 0; hh < 2; ++hh) {
            int pidx = mi*2 + hh;
            int p = mw*32 + mi*16 + hh*8 + g;
            float* orow = g_raw + ((size_t)(b*128 + p)*256 + y)*256 + x0 + nw*64;
#pragma unroll
            for (int nn = 0; nn < 8; ++nn) {
                float v0 = d[mi][nn][hh*2 + 0], v1 = d[mi][nn][hh*2 + 1];
                psum[pidx] += v0 + v1;
                psq[pidx]  += v0*v0 + v1*v1;
                *(float2*)(orow + nn*8 + q4*2) = make_float2(v0, v1);
            }
        }
    }
#pragma unroll
    for (int i = 0; i < 4; ++i) {
        psum[i] += __shfl_xor_sync(0xFFFFFFFF, psum[i], 1);
        psum[i] += __shfl_xor_sync(0xFFFFFFFF, psum[i], 2);
        psq[i]  += __shfl_xor_sync(0xFFFFFFFF, psq[i], 1);
        psq[i]  += __shfl_xor_sync(0xFFFFFFFF, psq[i], 2);
    }
    if (nw == 0 && q4 == 0) {
#pragma unroll
        for (int mi = 0; mi < 2; ++mi)
#pragma unroll
            for (int hh = 0; hh < 2; ++hh) {
                int p = mw*32 + mi*16 + hh*8 + g;
                s_sum[p] = psum[mi*2 + hh]; s_sq[p] = psq[mi*2 + hh];
            }
    }
    __syncthreads();
    if (nw == 1 && q4 == 0) {
#pragma unroll
        for (int mi = 0; mi < 2; ++mi)
#pragma unroll
            for (int hh = 0; hh < 2; ++hh) {
                int p = mw*32 + mi*16 + hh*8 + g;
                s_sum[p] += psum[mi*2 + hh]; s_sq[p] += psq[mi*2 + hh];
            }
    }
    __syncthreads();
    if (tid < 128) { g_ps1[tile*128 + tid] = s_sum[tid]; g_ps2[tile*128 + tid] = s_sq[tid]; }
}

// ---------------- final: BN4+ReLU, max over m, 1x1 + sigmoid ----------------
__global__ void final_kernel(const float* __restrict__ fw, float* __restrict__ out) {
    int gid = blockIdx.x * 256 + threadIdx.x;
    int b = gid >> 16, pix = gid & 65535;
    float acc = 0.f;
#pragma unroll 1
    for (int co = 0; co < 16; ++co) {
        float sc = g_sc[co], bi = g_bi[co];
        float mv = 0.f;
#pragma unroll
        for (int m = 0; m < 8; ++m) {
            float v = fmaf(g_raw[((b*16 + co)*8 + m)*HW + pix], sc, bi);
            mv = fmaxf(mv, v);
        }
        acc = fmaf(fw[co], mv, acc);
    }
    out[gid] = 1.0f / (1.0f + expf(-acc));
}

// ---------------- launch ----------------
extern "C" void kernel_launch(void* const* d_in, const int* in_sizes, int n_in,
                              void* d_out, int out_size) {
    const float* x  = (const float*)d_in[0];
    const float* lw = (const float*)d_in[1];
    const float* w1 = (const float*)d_in[2];
    const float* w2 = (const float*)d_in[3];
    const float* w3 = (const float*)d_in[4];
    const float* w4 = (const float*)d_in[5];
    const float* fw = (const float*)d_in[6];
    const float* g0 = (const float*)d_in[7];  const float* b0 = (const float*)d_in[8];
    const float* g1 = (const float*)d_in[9];  const float* b1 = (const float*)d_in[10];
    const float* g2 = (const float*)d_in[11]; const float* b2 = (const float*)d_in[12];
    const float* g3 = (const float*)d_in[13]; const float* b3 = (const float*)d_in[14];
    const float* g4 = (const float*)d_in[15]; const float* b4 = (const float*)d_in[16];
    float* out = (float*)d_out;

    const int SMEM = 132096;   // 2 x (32KB A + 32KB B) + 1KB sums
    cudaFuncSetAttribute(mma_conv_kernel, cudaFuncAttributeMaxDynamicSharedMemorySize, SMEM);

    rotate_lift_kernel<<<74, 256>>>(lw);
    lift_kernel<<<dim3(16,16,16), 256>>>(x);
    stats_partial_kernel<<<dim3(64,16), 256>>>();
    stats_final_kernel<<<1, 16>>>(g0, b0);

    pack_g_kernel<<<1600, 256>>>(w1);
    convert_kernel<<<dim3(9,260,2), 256>>>();
    mma_conv_kernel<<<1024, 256, SMEM>>>(0);
    stats_final_mma<<<16, 256>>>(g1, b1);

    pack_g_kernel<<<1600, 256>>>(w2);
    convert_kernel<<<dim3(9,260,2), 256>>>();
    mma_conv_kernel<<<1024, 256, SMEM>>>(0);
    stats_final_mma<<<16, 256>>>(g2, b2);

    pack_g_kernel<<<1600, 256>>>(w3);
    convert_kernel<<<dim3(9,260,2), 256>>>();
    mma_conv_kernel<<<1024, 256, SMEM>>>(0);
    stats_final_mma<<<16, 256>>>(g3, b3);

    pack_w4_kernel<<<64, 256>>>(w4);
    convert_kernel<<<dim3(9,260,2), 256>>>();
    mma_conv_kernel<<<1024, 256, SMEM>>>(1);
    stats_final_mma<<<16, 256>>>(g4, b4);

    final_kernel<<<512, 256>>>(fw, out);
}

// round 6
// speedup vs baseline: 8.9599x; 1.0586x over previous
#include <cuda_runtime.h>
#include <cuda_fp16.h>
#include <math.h>
#include <stdint.h>

#define HW 65536
#define PW 260

// ---------------- device scratch (allocation-free) ----------------
__device__ float  g_raw[2*128*HW];                        // lift output fp32 [b][c16][m8][y][x]
__device__ __align__(1024) __half g_actA[2*PW*PW*128];    // padded NHWC fp16 (ping)
__device__ __align__(1024) __half g_actB[2*PW*PW*128];    // padded NHWC fp16 (pong)
__device__ __align__(1024) __half g_wA[25*16384];         // gconv weights [tap][p][q] fp16
__device__ __align__(1024) __half g_wA4[16384];           // conv4 weights [p][q] fp16
__device__ float g_wrL[8*3*16*49];
__device__ float g_psum[16*64], g_psq[16*64];
__device__ float g_ps1[512*128], g_ps2[512*128];          // per-tile per-p partials
__device__ float g_sc[16], g_bi[16];

// ---------------- PTX helpers (sm_80-era, portable to plain sm_103) ----------------
__device__ __forceinline__ uint32_t smem_u32(const void* p) {
    uint32_t a;
    asm("{ .reg .u64 t; cvta.to.shared.u64 t, %1; cvt.u32.u64 %0, t; }" : "=r"(a) : "l"(p));
    return a;
}
__device__ __forceinline__ void cp_async16(uint32_t s, const void* g) {
    asm volatile("cp.async.cg.shared.global [%0], [%1], 16;" :: "r"(s), "l"(g) : "memory");
}
__device__ __forceinline__ void ldm_x4(uint32_t* r, uint32_t a) {
    asm volatile("ldmatrix.sync.aligned.m8n8.x4.shared.b16 {%0,%1,%2,%3}, [%4];"
        : "=r"(r[0]), "=r"(r[1]), "=r"(r[2]), "=r"(r[3]) : "r"(a));
}
__device__ __forceinline__ void mma16816(float* d, const uint32_t* a, const uint32_t* b) {
    asm volatile("mma.sync.aligned.m16n8k16.row.col.f32.f16.f16.f32 "
        "{%0,%1,%2,%3}, {%4,%5,%6,%7}, {%8,%9}, {%0,%1,%2,%3};"
        : "+f"(d[0]), "+f"(d[1]), "+f"(d[2]), "+f"(d[3])
        : "r"(a[0]), "r"(a[1]), "r"(a[2]), "r"(a[3]), "r"(b[0]), "r"(b[1]));
}

// ---------------- bilinear kernel rotation ----------------
__device__ __forceinline__ float rot_sample(const float* W, int k, float cs, float sn, int i, int j) {
    float c  = 0.5f * (float)(k - 1);
    float ys = (float)i - c, xs = (float)j - c;
    float sy = cs * ys - sn * xs + c;
    float sx = sn * ys + cs * xs + c;
    float fy = floorf(sy), fx = floorf(sx);
    int y0 = (int)fy, x0 = (int)fx;
    float wy = sy - fy, wx = sx - fx;
    float v00 = (y0   >= 0 && y0   < k && x0   >= 0 && x0   < k) ? W[y0*k + x0]       : 0.f;
    float v01 = (y0   >= 0 && y0   < k && x0+1 >= 0 && x0+1 < k) ? W[y0*k + x0 + 1]   : 0.f;
    float v10 = (y0+1 >= 0 && y0+1 < k && x0   >= 0 && x0   < k) ? W[(y0+1)*k + x0]   : 0.f;
    float v11 = (y0+1 >= 0 && y0+1 < k && x0+1 >= 0 && x0+1 < k) ? W[(y0+1)*k + x0+1] : 0.f;
    return v00*(1.f-wy)*(1.f-wx) + v01*(1.f-wy)*wx + v10*wy*(1.f-wx) + v11*wy*wx;
}

__global__ void rotate_lift_kernel(const float* __restrict__ lw) {
    int idx = blockIdx.x * 256 + threadIdx.x;
    if (idx >= 8*3*16*49) return;
    int j  = idx % 49;
    int co = (idx / 49) % 16;
    int ci = (idx / (49*16)) % 3;
    int m  = idx / (49*48);
    float th = (float)m * 0.78539816339744831f;
    float cs = cosf(th), sn = sinf(th);
    const float* W = lw + (co*3 + ci) * 49;
    g_wrL[((m*3 + ci)*16 + co)*49 + j] = rot_sample(W, 7, cs, sn, j/7, j%7);
}

__global__ void pack_g_kernel(const float* __restrict__ w) {
    int idx = blockIdx.x * 256 + threadIdx.x;   // 409600 exact
    int tap = idx >> 14;
    int p = (idx >> 7) & 127, q = idx & 127;
    int co = p >> 3, m = p & 7, ci = q >> 3, o = q & 7;
    int oo = (o - m) & 7;
    float th = (float)m * 0.78539816339744831f;
    float cs = cosf(th), sn = sinf(th);
    float v = rot_sample(w + ((co*16 + ci)*8 + oo)*25, 5, cs, sn, tap/5, tap%5);
    g_wA[tap*16384 + p*128 + q] = __float2half(v);
}

__global__ void pack_w4_kernel(const float* __restrict__ w4) {
    int idx = blockIdx.x * 256 + threadIdx.x;   // 16384
    int p = idx >> 7, q = idx & 127;
    int co = p >> 3, m = p & 7, ci = q >> 3, o = q & 7;
    g_wA4[idx] = __float2half(w4[(co*16 + ci)*8 + ((o - m) & 7)]);
}

// ---------------- lift conv (scalar fp32) -> g_raw ----------------
__global__ __launch_bounds__(256) void lift_kernel(const float* __restrict__ x) {
    int z = blockIdx.z; int b = z >> 3, m = z & 7;
    int x0 = blockIdx.x * 16, y0 = blockIdx.y * 16;
    int t = threadIdx.x; int tx = t & 15, ty = t >> 4;
    __shared__ float s_in[22*22];
    __shared__ float s_w[16*49];
    float acc[16];
#pragma unroll
    for (int i = 0; i < 16; ++i) acc[i] = 0.f;
#pragma unroll 1
    for (int ci = 0; ci < 3; ++ci) {
        const float* ip = x + (b*3 + ci) * HW;
        for (int idx = t; idx < 484; idx += 256) {
            int iy = idx / 22, ix = idx - iy*22;
            int gy = y0 + iy - 3; gy = gy < 0 ? -gy : (gy > 255 ? 510 - gy : gy);
            int gx = x0 + ix - 3; gx = gx < 0 ? -gx : (gx > 255 ? 510 - gx : gx);
            s_in[idx] = ip[gy*256 + gx];
        }
        const float* wp = g_wrL + (m*3 + ci) * 784;
        for (int idx = t; idx < 784; idx += 256) s_w[idx] = wp[idx];
        __syncthreads();
        float tap[49];
#pragma unroll
        for (int ky = 0; ky < 7; ++ky)
#pragma unroll
            for (int kx = 0; kx < 7; ++kx)
                tap[ky*7 + kx] = s_in[(ty+ky)*22 + tx + kx];
#pragma unroll
        for (int co = 0; co < 16; ++co) {
            float a = acc[co];
#pragma unroll
            for (int j = 0; j < 49; ++j) a = fmaf(tap[j], s_w[co*49 + j], a);
            acc[co] = a;
        }
        __syncthreads();
    }
    int pix = (y0 + ty) * 256 + x0 + tx;
#pragma unroll
    for (int co = 0; co < 16; ++co)
        g_raw[((b*16 + co)*8 + m)*HW + pix] = acc[co];
}

// ---------------- BN0 stats ----------------
__global__ void stats_partial_kernel() {
    int c = blockIdx.y, chunk = blockIdx.x, t = threadIdx.x;
    float s = 0.f, ss = 0.f;
    int base = chunk * 16384 + t;
#pragma unroll 4
    for (int k = 0; k < 64; ++k) {
        int e = base + k * 256;
        int b = e >> 19;
        int r = e & ((1 << 19) - 1);
        float v = g_raw[((b*16 + c) << 19) + r];
        s += v; ss += v * v;
    }
    __shared__ float sh1[256], sh2[256];
    sh1[t] = s; sh2[t] = ss;
    __syncthreads();
    for (int off = 128; off > 0; off >>= 1) {
        if (t < off) { sh1[t] += sh1[t + off]; sh2[t] += sh2[t + off]; }
        __syncthreads();
    }
    if (t == 0) { g_psum[c*64 + chunk] = sh1[0]; g_psq[c*64 + chunk] = sh2[0]; }
}

__global__ void stats_final_kernel(const float* __restrict__ g, const float* __restrict__ b) {
    int c = threadIdx.x;
    if (c >= 16) return;
    float s = 0.f, ss = 0.f;
    for (int i = 0; i < 64; ++i) { s += g_psum[c*64 + i]; ss += g_psq[c*64 + i]; }
    const float invN = 1.0f / 1048576.0f;
    float mean = s * invN;
    float var  = ss * invN - mean * mean;
    float sc = g[c] * rsqrtf(var + 1e-5f);
    g_sc[c] = sc;
    g_bi[c] = b[c] - mean * sc;
}

// BN stats from MMA epilogue partials (512 tiles x 128 p)
__global__ void stats_final_mma(const float* __restrict__ g, const float* __restrict__ b) {
    int c = blockIdx.x, t = threadIdx.x;
    float s = 0.f, ss = 0.f;
    for (int e = t; e < 4096; e += 256) {
        int idx = (e >> 3) * 128 + c*8 + (e & 7);
        s += g_ps1[idx]; ss += g_ps2[idx];
    }
    __shared__ float sh1[256], sh2[256];
    sh1[t] = s; sh2[t] = ss;
    __syncthreads();
    for (int off = 128; off > 0; off >>= 1) {
        if (t < off) { sh1[t] += sh1[t + off]; sh2[t] += sh2[t + off]; }
        __syncthreads();
    }
    if (t == 0) {
        const float invN = 1.0f / 1048576.0f;
        float mean = sh1[0] * invN;
        float var  = sh2[0] * invN - mean * mean;
        float sc = g[c] * rsqrtf(var + 1e-5f);
        g_sc[c] = sc;
        g_bi[c] = b[c] - mean * sc;
    }
}

// ---------------- convert0 (lift only): BN+ReLU+pad fp32->fp16 into g_actA ----------------
__global__ __launch_bounds__(256) void convert_kernel() {
    __shared__ __half s[128][33];
    int t = threadIdx.x;
    int py = blockIdx.y, b = blockIdx.z;
    int pxb = blockIdx.x * 32;
    int sy = py - 2; sy = sy < 0 ? -sy : (sy > 255 ? 510 - sy : sy);
    int lanepx = t & 31, wch = t >> 5;
    {
        int pg = pxb + lanepx;
        int sx = pg - 2; sx = sx < 0 ? -sx : (sx > 255 ? 510 - sx : sx);
        bool ok = pg < PW;
        const float* rp = g_raw + (size_t)b*128*HW + sy*256 + sx;
#pragma unroll
        for (int i = 0; i < 16; ++i) {
            int ch = wch + i*8;
            float f = ok ? rp[(size_t)ch * HW] : 0.f;
            f = fmaxf(fmaf(f, g_sc[ch >> 3], g_bi[ch >> 3]), 0.f);
            s[ch][lanepx] = __float2half(f);
        }
    }
    __syncthreads();
#pragma unroll
    for (int i = 0; i < 2; ++i) {
        int idx = i*256 + t;
        int px = idx >> 4, qc = idx & 15;
        int pg = pxb + px;
        if (pg >= PW) continue;
        __half h[8];
#pragma unroll
        for (int k = 0; k < 8; ++k) h[k] = s[qc*8 + k][px];
        *(uint4*)(g_actA + ((size_t)(b*PW + py)*PW + pg)*128 + qc*8) = *(uint4*)h;
    }
}

// ---------------- BN in-place on fp16 act: border pass (reads raw interior) ----------------
__global__ void bn_border_kernel(int which) {   // grid (2064, 2), block 128
    __half* act = which ? g_actB : g_actA;
    int i = blockIdx.x, b = blockIdx.y, ch = threadIdx.x;
    int py, px;
    if (i < 520)       { py = i / 260;              px = i % 260; }
    else if (i < 1040) { int j = i - 520; py = 258 + j / 260; px = j % 260; }
    else               { int j = i - 1040; py = 2 + (j >> 2); int c = j & 3; px = (c & 1) + ((c >> 1) * 258); }
    int uy = py - 2; uy = uy < 0 ? -uy : (uy > 255 ? 510 - uy : uy);
    int ux = px - 2; ux = ux < 0 ? -ux : (ux > 255 ? 510 - ux : ux);
    float f = __half2float(act[((size_t)(b*PW + uy + 2)*PW + ux + 2)*128 + ch]);
    f = fmaxf(fmaf(f, g_sc[ch >> 3], g_bi[ch >> 3]), 0.f);
    act[((size_t)(b*PW + py)*PW + px)*128 + ch] = __float2half(f);
}

// ---------------- BN in-place on fp16 act: interior RMW ----------------
__global__ void bn_interior_kernel(int which) {  // grid 8192, block 256
    __half* act = which ? g_actB : g_actA;
    int gid = blockIdx.x * 256 + threadIdx.x;    // 2*65536*16
    int qc = gid & 15; int pix = (gid >> 4) & 65535; int b = gid >> 20;
    int y = pix >> 8, x = pix & 255;
    __half* p = act + ((size_t)(b*PW + y + 2)*PW + x + 2)*128 + qc*8;
    uint4 v = *(uint4*)p; __half* h = (__half*)&v;
#pragma unroll
    for (int k = 0; k < 8; ++k) {
        int ch = qc*8 + k;
        float f = __half2float(h[k]);
        f = fmaxf(fmaf(f, g_sc[ch >> 3], g_bi[ch >> 3]), 0.f);
        h[k] = __float2half(f);
    }
    *(uint4*)p = v;
}

// ---------------- mma.sync implicit-GEMM conv with row reuse ----------------
// CTA: full output row, 128p x 256px. 512 thr = 16 warps (4 mw x 4 nw of 32p x 64px).
// dir=0: actA->actB; dir=1: actB->actA. Output = raw fp16 NHWC into padded interior.
__global__ __launch_bounds__(512, 1) void mma_conv_kernel(int dir, int is1x1) {
    extern __shared__ __align__(256) char dsm[];
    uint32_t sbase = smem_u32(dsm);
    const uint32_t BST = 66560;                    // one padded row: 260 px x 256B
    uint32_t Wbase = sbase + 2*BST;                // 2 weight stages x 32768
    float* s_sum = (float*)(dsm + 198656);         // [4][128]
    float* s_sq  = (float*)(dsm + 198656 + 2048);

    const __half* actin = dir ? g_actB : g_actA;
    __half* actout      = dir ? g_actA : g_actB;

    int tid = threadIdx.x, w = tid >> 5, lane = tid & 31;
    int mw = w & 3, nw = w >> 2;
    int tile = blockIdx.x; int b = tile >> 8, y = tile & 255;
    int ntap = is1x1 ? 1 : 25;
    const __half* wsrc = is1x1 ? g_wA4 : g_wA;
    const __half* actb = actin + (size_t)b * PW * PW * 128;

    float d[2][8][4];
#pragma unroll
    for (int mi = 0; mi < 2; ++mi)
#pragma unroll
        for (int nn = 0; nn < 8; ++nn)
#pragma unroll
            for (int k = 0; k < 4; ++k) d[mi][nn][k] = 0.f;

    // load one padded act row (260 px) into stage stg
    auto load_brow = [&](int ky, int stg) {
        const __half* src = actb + (size_t)(y + ky) * PW * 128;
        uint32_t Bb = sbase + stg * BST;
        for (int id = tid; id < 4160; id += 512) {
            int r = id >> 4, c = id & 15;
            cp_async16(Bb + r*256 + ((c ^ (r & 7)) * 16), src + id*8);
        }
    };
    auto load_w = [&](int tp, int stg) {
        const __half* src = wsrc + tp * 16384;
        uint32_t Ab = Wbase + stg * 32768;
#pragma unroll
        for (int it = 0; it < 4; ++it) {
            int id = it*512 + tid; int r = id >> 4, c = id & 15;
            cp_async16(Ab + r*256 + ((c ^ (r & 7)) * 16), src + id*8);
        }
    };

    load_brow(is1x1 ? 2 : 0, 0);
    load_w(0, 0);
    asm volatile("cp.async.commit_group;" ::: "memory");

#pragma unroll 1
    for (int t = 0; t < ntap; ++t) {
        int ky = is1x1 ? 2 : t / 5, kx = is1x1 ? 2 : t % 5;
        if (t + 1 < ntap) {
            if ((t + 1) % 5 == 0) load_brow((t + 1) / 5, ((t + 1) / 5) & 1);
            load_w(t + 1, (t + 1) & 1);
        }
        asm volatile("cp.async.commit_group;" ::: "memory");
        if (t + 1 < ntap) { asm volatile("cp.async.wait_group 1;" ::: "memory"); }
        else              { asm volatile("cp.async.wait_group 0;" ::: "memory"); }
        __syncthreads();
        uint32_t Bb = sbase + (uint32_t)(ky & 1) * BST;
        uint32_t Ab = Wbase + (uint32_t)(t & 1) * 32768;
        int arb = mw*32 + (lane & 15);
        int acs = lane >> 4;
        int brb = kx + nw*64 + (lane & 7) + ((lane >> 4) << 3);
        int bcs = (lane >> 3) & 1;
#pragma unroll
        for (int ks = 0; ks < 8; ++ks) {
            uint32_t a[2][4];
#pragma unroll
            for (int mi = 0; mi < 2; ++mi) {
                int r = arb + mi*16, c = ks*2 + acs;
                ldm_x4(a[mi], Ab + r*256 + ((c ^ (r & 7)) * 16));
            }
            uint32_t bf[8][2];
#pragma unroll
            for (int nj = 0; nj < 4; ++nj) {
                int r = brb + nj*16, c = ks*2 + bcs;
                uint32_t q[4];
                ldm_x4(q, Bb + r*256 + ((c ^ (r & 7)) * 16));
                bf[nj*2][0] = q[0]; bf[nj*2][1] = q[1];
                bf[nj*2+1][0] = q[2]; bf[nj*2+1][1] = q[3];
            }
#pragma unroll
            for (int mi = 0; mi < 2; ++mi)
#pragma unroll
                for (int nn = 0; nn < 8; ++nn)
                    mma16816(d[mi][nn], a[mi], bf[nn]);
        }
        __syncthreads();
    }

    // ---- stats: deterministic per-p sums ----
    int g = lane >> 2, q4 = lane & 3;
    float psum[4], psq[4];
#pragma unroll
    for (int i = 0; i < 4; ++i) { psum[i] = 0.f; psq[i] = 0.f; }
#pragma unroll
    for (int mi = 0; mi < 2; ++mi)
#pragma unroll
        for (int hh = 0; hh < 2; ++hh) {
            int pidx = mi*2 + hh;
#pragma unroll
            for (int nn = 0; nn < 8; ++nn) {
                float v0 = d[mi][nn][hh*2 + 0], v1 = d[mi][nn][hh*2 + 1];
                psum[pidx] += v0 + v1;
                psq[pidx]  += v0*v0 + v1*v1;
            }
        }
#pragma unroll
    for (int i = 0; i < 4; ++i) {
        psum[i] += __shfl_xor_sync(0xFFFFFFFF, psum[i], 1);
        psum[i] += __shfl_xor_sync(0xFFFFFFFF, psum[i], 2);
        psq[i]  += __shfl_xor_sync(0xFFFFFFFF, psq[i], 1);
        psq[i]  += __shfl_xor_sync(0xFFFFFFFF, psq[i], 2);
    }
    if (q4 == 0) {
#pragma unroll
        for (int mi = 0; mi < 2; ++mi)
#pragma unroll
            for (int hh = 0; hh < 2; ++hh) {
                int p = mw*32 + mi*16 + hh*8 + g;
                s_sum[nw*128 + p] = psum[mi*2 + hh];
                s_sq[nw*128 + p]  = psq[mi*2 + hh];
            }
    }
    // ---- transpose D -> fp16 NHWC via SMEM (reuse B stages), write padded interior ----
    __half* s_out = (__half*)dsm;                  // stride 136 halves (272B) per px
#pragma unroll
    for (int mi = 0; mi < 2; ++mi)
#pragma unroll
        for (int hh = 0; hh < 2; ++hh) {
            int p = mw*32 + mi*16 + hh*8 + g;
#pragma unroll
            for (int nn = 0; nn < 8; ++nn) {
                int px = nw*64 + nn*8 + q4*2;
                s_out[(size_t)px*136 + p]       = __float2half(d[mi][nn][hh*2 + 0]);
                s_out[(size_t)(px+1)*136 + p]   = __float2half(d[mi][nn][hh*2 + 1]);
            }
        }
    __syncthreads();
    if (tid < 128) {
        float s = 0.f, ss = 0.f;
#pragma unroll
        for (int k = 0; k < 4; ++k) { s += s_sum[k*128 + tid]; ss += s_sq[k*128 + tid]; }
        g_ps1[tile*128 + tid] = s; g_ps2[tile*128 + tid] = ss;
    }
    __half* ob = actout + ((size_t)(b*PW + y + 2)*PW + 2)*128;
    for (int id = tid; id < 4096; id += 512) {
        int px = id >> 4, qc = id & 15;
        *(uint4*)(ob + (size_t)px*128 + qc*8) = *(uint4*)((char*)dsm + px*272 + qc*16);
    }
}

// ---------------- final: BN4+ReLU, max over m, 1x1 + sigmoid (reads conv4 raw fp16 in actA) ----------------
__global__ void final_kernel(const float* __restrict__ fw, float* __restrict__ out) {
    int gid = blockIdx.x * 256 + threadIdx.x;    // 131072
    int b = gid >> 16, pix = gid & 65535;
    int y = pix >> 8, x = pix & 255;
    const __half* p = g_actA + ((size_t)(b*PW + y + 2)*PW + x + 2)*128;
    float acc = 0.f;
#pragma unroll 1
    for (int co = 0; co < 16; ++co) {
        float sc = g_sc[co], bi = g_bi[co];
        uint4 v = *(const uint4*)(p + co*8);
        const __half* h = (const __half*)&v;
        float mv = 0.f;
#pragma unroll
        for (int m = 0; m < 8; ++m) {
            float f = fmaf(__half2float(h[m]), sc, bi);
            mv = fmaxf(mv, f);
        }
        acc = fmaf(fw[co], mv, acc);
    }
    out[gid] = 1.0f / (1.0f + expf(-acc));
}

// ---------------- launch ----------------
extern "C" void kernel_launch(void* const* d_in, const int* in_sizes, int n_in,
                              void* d_out, int out_size) {
    const float* x  = (const float*)d_in[0];
    const float* lw = (const float*)d_in[1];
    const float* w1 = (const float*)d_in[2];
    const float* w2 = (const float*)d_in[3];
    const float* w3 = (const float*)d_in[4];
    const float* w4 = (const float*)d_in[5];
    const float* fw = (const float*)d_in[6];
    const float* g0 = (const float*)d_in[7];  const float* b0 = (const float*)d_in[8];
    const float* g1 = (const float*)d_in[9];  const float* b1 = (const float*)d_in[10];
    const float* g2 = (const float*)d_in[11]; const float* b2 = (const float*)d_in[12];
    const float* g3 = (const float*)d_in[13]; const float* b3 = (const float*)d_in[14];
    const float* g4 = (const float*)d_in[15]; const float* b4 = (const float*)d_in[16];
    float* out = (float*)d_out;

    const int SMEM = 202752;   // 2 row stages (133120) + 2 weight stages (65536) + sums (4096)
    cudaFuncSetAttribute(mma_conv_kernel, cudaFuncAttributeMaxDynamicSharedMemorySize, SMEM);

    // lift -> BN0 stats -> convert0 (fp32 -> padded fp16 actA)
    rotate_lift_kernel<<<74, 256>>>(lw);
    lift_kernel<<<dim3(16,16,16), 256>>>(x);
    stats_partial_kernel<<<dim3(64,16), 256>>>();
    stats_final_kernel<<<1, 16>>>(g0, b0);
    convert_kernel<<<dim3(9,260,2), 256>>>();

    // layer1: actA -> actB (raw fp16), BN1 in place
    pack_g_kernel<<<1600, 256>>>(w1);
    mma_conv_kernel<<<512, 512, SMEM>>>(0, 0);
    stats_final_mma<<<16, 256>>>(g1, b1);
    bn_border_kernel<<<dim3(2064,2), 128>>>(1);
    bn_interior_kernel<<<8192, 256>>>(1);

    // layer2: actB -> actA, BN2 in place
    pack_g_kernel<<<1600, 256>>>(w2);
    mma_conv_kernel<<<512, 512, SMEM>>>(1, 0);
    stats_final_mma<<<16, 256>>>(g2, b2);
    bn_border_kernel<<<dim3(2064,2), 128>>>(0);
    bn_interior_kernel<<<8192, 256>>>(0);

    // layer3: actA -> actB, BN3 in place
    pack_g_kernel<<<1600, 256>>>(w3);
    mma_conv_kernel<<<512, 512, SMEM>>>(0, 0);
    stats_final_mma<<<16, 256>>>(g3, b3);
    bn_border_kernel<<<dim3(2064,2), 128>>>(1);
    bn_interior_kernel<<<8192, 256>>>(1);

    // conv4 (1x1): actB -> actA raw; BN4 folded into final
    pack_w4_kernel<<<64, 256>>>(w4);
    mma_conv_kernel<<<512, 512, SMEM>>>(1, 1);
    stats_final_mma<<<16, 256>>>(g4, b4);

    final_kernel<<<512, 256>>>(fw, out);
}

// round 7
// speedup vs baseline: 8.9750x; 1.0017x over previous
#include <cuda_runtime.h>
#include <cuda_fp16.h>
#include <math.h>
#include <stdint.h>

#define HW 65536
#define PW 260

// ---------------- device scratch (allocation-free) ----------------
__device__ float  g_raw[2*128*HW];                        // lift output fp32 [b][c16][m8][y][x]
__device__ __align__(1024) __half g_actA[2*PW*PW*128];    // padded NHWC fp16 RAW (ping)
__device__ __align__(1024) __half g_actB[2*PW*PW*128];    // padded NHWC fp16 RAW (pong)
__device__ __align__(1024) __half g_wA[25*16384];         // gconv weights [tap][p][q] fp16
__device__ __align__(1024) __half g_wA4[16384];           // conv4 weights [p][q] fp16
__device__ float g_wrL[8*3*16*49];
__device__ float g_psum[16*64], g_psq[16*64];
__device__ float g_ps1[1024*128], g_ps2[1024*128];        // per-tile per-p partials
__device__ float g_sc[16], g_bi[16];

// ---------------- PTX helpers (sm_80-era, portable to plain sm_103) ----------------
__device__ __forceinline__ uint32_t smem_u32(const void* p) {
    uint32_t a;
    asm("{ .reg .u64 t; cvta.to.shared.u64 t, %1; cvt.u32.u64 %0, t; }" : "=r"(a) : "l"(p));
    return a;
}
__device__ __forceinline__ void cp_async16(uint32_t s, const void* g) {
    asm volatile("cp.async.cg.shared.global [%0], [%1], 16;" :: "r"(s), "l"(g) : "memory");
}
__device__ __forceinline__ void ldm_x4(uint32_t* r, uint32_t a) {
    asm volatile("ldmatrix.sync.aligned.m8n8.x4.shared.b16 {%0,%1,%2,%3}, [%4];"
        : "=r"(r[0]), "=r"(r[1]), "=r"(r[2]), "=r"(r[3]) : "r"(a));
}
__device__ __forceinline__ void mma16816(float* d, const uint32_t* a, const uint32_t* b) {
    asm volatile("mma.sync.aligned.m16n8k16.row.col.f32.f16.f16.f32 "
        "{%0,%1,%2,%3}, {%4,%5,%6,%7}, {%8,%9}, {%0,%1,%2,%3};"
        : "+f"(d[0]), "+f"(d[1]), "+f"(d[2]), "+f"(d[3])
        : "r"(a[0]), "r"(a[1]), "r"(a[2]), "r"(a[3]), "r"(b[0]), "r"(b[1]));
}

// ---------------- bilinear kernel rotation ----------------
__device__ __forceinline__ float rot_sample(const float* W, int k, float cs, float sn, int i, int j) {
    float c  = 0.5f * (float)(k - 1);
    float ys = (float)i - c, xs = (float)j - c;
    float sy = cs * ys - sn * xs + c;
    float sx = sn * ys + cs * xs + c;
    float fy = floorf(sy), fx = floorf(sx);
    int y0 = (int)fy, x0 = (int)fx;
    float wy = sy - fy, wx = sx - fx;
    float v00 = (y0   >= 0 && y0   < k && x0   >= 0 && x0   < k) ? W[y0*k + x0]       : 0.f;
    float v01 = (y0   >= 0 && y0   < k && x0+1 >= 0 && x0+1 < k) ? W[y0*k + x0 + 1]   : 0.f;
    float v10 = (y0+1 >= 0 && y0+1 < k && x0   >= 0 && x0   < k) ? W[(y0+1)*k + x0]   : 0.f;
    float v11 = (y0+1 >= 0 && y0+1 < k && x0+1 >= 0 && x0+1 < k) ? W[(y0+1)*k + x0+1] : 0.f;
    return v00*(1.f-wy)*(1.f-wx) + v01*(1.f-wy)*wx + v10*wy*(1.f-wx) + v11*wy*wx;
}

__global__ void rotate_lift_kernel(const float* __restrict__ lw) {
    int idx = blockIdx.x * 256 + threadIdx.x;
    if (idx >= 8*3*16*49) return;
    int j  = idx % 49;
    int co = (idx / 49) % 16;
    int ci = (idx / (49*16)) % 3;
    int m  = idx / (49*48);
    float th = (float)m * 0.78539816339744831f;
    float cs = cosf(th), sn = sinf(th);
    const float* W = lw + (co*3 + ci) * 49;
    g_wrL[((m*3 + ci)*16 + co)*49 + j] = rot_sample(W, 7, cs, sn, j/7, j%7);
}

__global__ void pack_g_kernel(const float* __restrict__ w) {
    int idx = blockIdx.x * 256 + threadIdx.x;   // 409600 exact
    int tap = idx >> 14;
    int p = (idx >> 7) & 127, q = idx & 127;
    int co = p >> 3, m = p & 7, ci = q >> 3, o = q & 7;
    int oo = (o - m) & 7;
    float th = (float)m * 0.78539816339744831f;
    float cs = cosf(th), sn = sinf(th);
    float v = rot_sample(w + ((co*16 + ci)*8 + oo)*25, 5, cs, sn, tap/5, tap%5);
    g_wA[tap*16384 + p*128 + q] = __float2half(v);
}

__global__ void pack_w4_kernel(const float* __restrict__ w4) {
    int idx = blockIdx.x * 256 + threadIdx.x;   // 16384
    int p = idx >> 7, q = idx & 127;
    int co = p >> 3, m = p & 7, ci = q >> 3, o = q & 7;
    g_wA4[idx] = __float2half(w4[(co*16 + ci)*8 + ((o - m) & 7)]);
}

// ---------------- lift conv (scalar fp32) -> g_raw ----------------
__global__ __launch_bounds__(256) void lift_kernel(const float* __restrict__ x) {
    int z = blockIdx.z; int b = z >> 3, m = z & 7;
    int x0 = blockIdx.x * 16, y0 = blockIdx.y * 16;
    int t = threadIdx.x; int tx = t & 15, ty = t >> 4;
    __shared__ float s_in[22*22];
    __shared__ float s_w[16*49];
    float acc[16];
#pragma unroll
    for (int i = 0; i < 16; ++i) acc[i] = 0.f;
#pragma unroll 1
    for (int ci = 0; ci < 3; ++ci) {
        const float* ip = x + (b*3 + ci) * HW;
        for (int idx = t; idx < 484; idx += 256) {
            int iy = idx / 22, ix = idx - iy*22;
            int gy = y0 + iy - 3; gy = gy < 0 ? -gy : (gy > 255 ? 510 - gy : gy);
            int gx = x0 + ix - 3; gx = gx < 0 ? -gx : (gx > 255 ? 510 - gx : gx);
            s_in[idx] = ip[gy*256 + gx];
        }
        const float* wp = g_wrL + (m*3 + ci) * 784;
        for (int idx = t; idx < 784; idx += 256) s_w[idx] = wp[idx];
        __syncthreads();
        float tap[49];
#pragma unroll
        for (int ky = 0; ky < 7; ++ky)
#pragma unroll
            for (int kx = 0; kx < 7; ++kx)
                tap[ky*7 + kx] = s_in[(ty+ky)*22 + tx + kx];
#pragma unroll
        for (int co = 0; co < 16; ++co) {
            float a = acc[co];
#pragma unroll
            for (int j = 0; j < 49; ++j) a = fmaf(tap[j], s_w[co*49 + j], a);
            acc[co] = a;
        }
        __syncthreads();
    }
    int pix = (y0 + ty) * 256 + x0 + tx;
#pragma unroll
    for (int co = 0; co < 16; ++co)
        g_raw[((b*16 + co)*8 + m)*HW + pix] = acc[co];
}

// ---------------- BN0 stats on g_raw ----------------
__global__ void stats_partial_kernel() {
    int c = blockIdx.y, chunk = blockIdx.x, t = threadIdx.x;
    float s = 0.f, ss = 0.f;
    int base = chunk * 16384 + t;
#pragma unroll 4
    for (int k = 0; k < 64; ++k) {
        int e = base + k * 256;
        int b = e >> 19;
        int r = e & ((1 << 19) - 1);
        float v = g_raw[((b*16 + c) << 19) + r];
        s += v; ss += v * v;
    }
    __shared__ float sh1[256], sh2[256];
    sh1[t] = s; sh2[t] = ss;
    __syncthreads();
    for (int off = 128; off > 0; off >>= 1) {
        if (t < off) { sh1[t] += sh1[t + off]; sh2[t] += sh2[t + off]; }
        __syncthreads();
    }
    if (t == 0) { g_psum[c*64 + chunk] = sh1[0]; g_psq[c*64 + chunk] = sh2[0]; }
}

__global__ void stats_final_kernel(const float* __restrict__ g, const float* __restrict__ b) {
    int c = threadIdx.x;
    if (c >= 16) return;
    float s = 0.f, ss = 0.f;
    for (int i = 0; i < 64; ++i) { s += g_psum[c*64 + i]; ss += g_psq[c*64 + i]; }
    const float invN = 1.0f / 1048576.0f;
    float mean = s * invN;
    float var  = ss * invN - mean * mean;
    float sc = g[c] * rsqrtf(var + 1e-5f);
    g_sc[c] = sc;
    g_bi[c] = b[c] - mean * sc;
}

// BN stats from MMA epilogue partials (1024 tiles x 128 p)
__global__ void stats_final_mma(const float* __restrict__ g, const float* __restrict__ b) {
    int c = blockIdx.x, t = threadIdx.x;
    float s = 0.f, ss = 0.f;
    for (int e = t; e < 8192; e += 256) {
        int idx = (e >> 3) * 128 + c*8 + (e & 7);
        s += g_ps1[idx]; ss += g_ps2[idx];
    }
    __shared__ float sh1[256], sh2[256];
    sh1[t] = s; sh2[t] = ss;
    __syncthreads();
    for (int off = 128; off > 0; off >>= 1) {
        if (t < off) { sh1[t] += sh1[t + off]; sh2[t] += sh2[t + off]; }
        __syncthreads();
    }
    if (t == 0) {
        const float invN = 1.0f / 1048576.0f;
        float mean = sh1[0] * invN;
        float var  = sh2[0] * invN - mean * mean;
        float sc = g[c] * rsqrtf(var + 1e-5f);
        g_sc[c] = sc;
        g_bi[c] = b[c] - mean * sc;
    }
}

// ---------------- convert0: RAW fp32 -> padded fp16 NHWC (reflect borders) ----------------
__global__ __launch_bounds__(256) void convert_kernel() {
    __shared__ __half s[128][33];
    int t = threadIdx.x;
    int py = blockIdx.y, b = blockIdx.z;
    int pxb = blockIdx.x * 32;
    int sy = py - 2; sy = sy < 0 ? -sy : (sy > 255 ? 510 - sy : sy);
    int lanepx = t & 31, wch = t >> 5;
    {
        int pg = pxb + lanepx;
        int sx = pg - 2; sx = sx < 0 ? -sx : (sx > 255 ? 510 - sx : sx);
        bool ok = pg < PW;
        const float* rp = g_raw + (size_t)b*128*HW + sy*256 + sx;
#pragma unroll
        for (int i = 0; i < 16; ++i) {
            int ch = wch + i*8;
            float f = ok ? rp[(size_t)ch * HW] : 0.f;
            s[ch][lanepx] = __float2half(f);
        }
    }
    __syncthreads();
#pragma unroll
    for (int i = 0; i < 2; ++i) {
        int idx = i*256 + t;
        int px = idx >> 4, qc = idx & 15;
        int pg = pxb + px;
        if (pg >= PW) continue;
        __half h[8];
#pragma unroll
        for (int k = 0; k < 8; ++k) h[k] = s[qc*8 + k][px];
        *(uint4*)(g_actA + ((size_t)(b*PW + py)*PW + pg)*128 + qc*8) = *(uint4*)h;
    }
}

// ---------------- raw mirror border copy (after each mma layer) ----------------
__global__ void border_copy_kernel(int which) {   // grid (129, 2), block 256
    __half* act = which ? g_actB : g_actA;
    int gid = blockIdx.x * 256 + threadIdx.x;
    if (gid >= 2064*16) return;
    int b = blockIdx.y;
    int i = gid >> 4, qc = gid & 15;
    int py, px;
    if (i < 520)       { py = i / 260;                 px = i % 260; }
    else if (i < 1040) { int j = i - 520; py = 258 + j / 260; px = j % 260; }
    else               { int j = i - 1040; py = 2 + (j >> 2); int c = j & 3; px = (c & 1) + ((c >> 1) * 258); }
    int uy = py - 2; uy = uy < 0 ? -uy : (uy > 255 ? 510 - uy : uy);
    int ux = px - 2; ux = ux < 0 ? -ux : (ux > 255 ? 510 - ux : ux);
    uint4 v = *(uint4*)(act + ((size_t)(b*PW + uy + 2)*PW + ux + 2)*128 + qc*8);
    *(uint4*)(act + ((size_t)(b*PW + py)*PW + px)*128 + qc*8) = v;
}

// ---------------- mma.sync implicit-GEMM conv, 128px tiles, fused input BN ----------------
// grid 1024; 256 thr = 8 warps (mw=w&3: 32p, nw=w>>2: 64px). Acts stored RAW; BN+ReLU
// applied in SMEM once per ky window using current g_sc/g_bi (stats of the input layer).
#define BSTG 33792   // 132 px x 256 B
__global__ __launch_bounds__(256, 1) void mma_conv_kernel(int dir, int is1x1) {
    extern __shared__ __align__(256) char dsm[];
    uint32_t sbase = smem_u32(dsm);
    uint32_t Wbase = sbase + 2*BSTG;
    float* s_sum = (float*)(dsm + 133120);   // [2][128]
    float* s_sq  = (float*)(dsm + 134144);

    const __half* actin = dir ? g_actB : g_actA;
    __half* actout      = dir ? g_actA : g_actB;

    int tid = threadIdx.x, w = tid >> 5, lane = tid & 31;
    int mw = w & 3, nw = w >> 2;
    int tile = blockIdx.x;
    int b = tile >> 9, rem = tile & 511;
    int y = rem >> 1, xh = (rem & 1) << 7;
    int ntap = is1x1 ? 1 : 25;
    const __half* wsrc = is1x1 ? g_wA4 : g_wA;
    const __half* actb = actin + (size_t)b * PW * PW * 128;

    float d[2][8][4];
#pragma unroll
    for (int mi = 0; mi < 2; ++mi)
#pragma unroll
        for (int nn = 0; nn < 8; ++nn)
#pragma unroll
            for (int k = 0; k < 4; ++k) d[mi][nn][k] = 0.f;

    auto load_brow = [&](int ky, int stg) {
        const __half* src = actb + ((size_t)(y + ky) * PW + xh) * 128;
        uint32_t Bb = sbase + (uint32_t)stg * BSTG;
        for (int id = tid; id < 2112; id += 256) {
            int r = id >> 4, c = id & 15;
            cp_async16(Bb + r*256 + ((c ^ (r & 7)) * 16), src + id*8);
        }
    };
    auto load_w = [&](int tp, int stg) {
        const __half* src = wsrc + tp * 16384;
        uint32_t Ab = Wbase + (uint32_t)stg * 32768;
#pragma unroll
        for (int it = 0; it < 8; ++it) {
            int id = it*256 + tid; int r = id >> 4, c = id & 15;
            cp_async16(Ab + r*256 + ((c ^ (r & 7)) * 16), src + id*8);
        }
    };
    // BN+ReLU transform of a staged B window (raw fp16 -> normalized fp16), fp32 math
    auto bn_stage = [&](int stg) {
        uint32_t Bb = sbase + (uint32_t)stg * BSTG;
        for (int id = tid; id < 2112; id += 256) {
            int r = id >> 4, c = id & 15;
            uint32_t ad = Bb + r*256 + ((c ^ (r & 7)) * 16);
            uint4 v; asm volatile("ld.shared.v4.b32 {%0,%1,%2,%3}, [%4];"
                : "=r"(v.x), "=r"(v.y), "=r"(v.z), "=r"(v.w) : "r"(ad));
            __half* h = (__half*)&v;
            float sc = g_sc[c], bi = g_bi[c];
#pragma unroll
            for (int k = 0; k < 8; ++k)
                h[k] = __float2half(fmaxf(fmaf(__half2float(h[k]), sc, bi), 0.f));
            asm volatile("st.shared.v4.b32 [%0], {%1,%2,%3,%4};"
                :: "r"(ad), "r"(v.x), "r"(v.y), "r"(v.z), "r"(v.w));
        }
    };

    load_brow(is1x1 ? 2 : 0, 0);
    load_w(0, 0);
    asm volatile("cp.async.commit_group;" ::: "memory");

#pragma unroll 1
    for (int t = 0; t < ntap; ++t) {
        int ky = is1x1 ? 2 : t / 5, kx = is1x1 ? 2 : t % 5;
        int bstg = is1x1 ? 0 : (ky & 1);
        if (t + 1 < ntap) {
            if ((t + 1) % 5 == 0) load_brow((t + 1) / 5, ((t + 1) / 5) & 1);
            load_w(t + 1, (t + 1) & 1);
        }
        asm volatile("cp.async.commit_group;" ::: "memory");
        if (t + 1 < ntap) { asm volatile("cp.async.wait_group 1;" ::: "memory"); }
        else              { asm volatile("cp.async.wait_group 0;" ::: "memory"); }
        __syncthreads();
        if ((t % 5) == 0) {          // new B window: apply BN+ReLU in smem
            bn_stage(bstg);
            __syncthreads();
        }
        uint32_t Bb = sbase + (uint32_t)bstg * BSTG;
        uint32_t Ab = Wbase + (uint32_t)(t & 1) * 32768;
        int arb = mw*32 + (lane & 15);
        int acs = lane >> 4;
        int brb = kx + nw*64 + (lane & 7) + ((lane >> 4) << 3);
        int bcs = (lane >> 3) & 1;
#pragma unroll
        for (int ks = 0; ks < 8; ++ks) {
            uint32_t a[2][4];
#pragma unroll
            for (int mi = 0; mi < 2; ++mi) {
                int r = arb + mi*16, c = ks*2 + acs;
                ldm_x4(a[mi], Ab + r*256 + ((c ^ (r & 7)) * 16));
            }
            uint32_t bf[8][2];
#pragma unroll
            for (int nj = 0; nj < 4; ++nj) {
                int r = brb + nj*16, c = ks*2 + bcs;
                uint32_t q[4];
                ldm_x4(q, Bb + r*256 + ((c ^ (r & 7)) * 16));
                bf[nj*2][0] = q[0]; bf[nj*2][1] = q[1];
                bf[nj*2+1][0] = q[2]; bf[nj*2+1][1] = q[3];
            }
#pragma unroll
            for (int mi = 0; mi < 2; ++mi)
#pragma unroll
                for (int nn = 0; nn < 8; ++nn)
                    mma16816(d[mi][nn], a[mi], bf[nn]);
        }
        __syncthreads();
    }

    // ---- deterministic per-p sums ----
    int g = lane >> 2, q4 = lane & 3;
    float psum[4], psq[4];
#pragma unroll
    for (int i = 0; i < 4; ++i) { psum[i] = 0.f; psq[i] = 0.f; }
#pragma unroll
    for (int mi = 0; mi < 2; ++mi)
#pragma unroll
        for (int hh = 0; hh < 2; ++hh) {
            int pidx = mi*2 + hh;
#pragma unroll
            for (int nn = 0; nn < 8; ++nn) {
                float v0 = d[mi][nn][hh*2 + 0], v1 = d[mi][nn][hh*2 + 1];
                psum[pidx] += v0 + v1;
                psq[pidx]  += v0*v0 + v1*v1;
            }
        }
#pragma unroll
    for (int i = 0; i < 4; ++i) {
        psum[i] += __shfl_xor_sync(0xFFFFFFFF, psum[i], 1);
        psum[i] += __shfl_xor_sync(0xFFFFFFFF, psum[i], 2);
        psq[i]  += __shfl_xor_sync(0xFFFFFFFF, psq[i], 1);
        psq[i]  += __shfl_xor_sync(0xFFFFFFFF, psq[i], 2);
    }
    if (q4 == 0) {
#pragma unroll
        for (int mi = 0; mi < 2; ++mi)
#pragma unroll
            for (int hh = 0; hh < 2; ++hh) {
                int p = mw*32 + mi*16 + hh*8 + g;
                s_sum[nw*128 + p] = psum[mi*2 + hh];
                s_sq[nw*128 + p]  = psq[mi*2 + hh];
            }
    }
    // ---- transpose D -> raw fp16 NHWC via smem (reuse B stages) ----
    __half* s_out = (__half*)dsm;                  // 128 px x 136-half stride (34816 B)
#pragma unroll
    for (int mi = 0; mi < 2; ++mi)
#pragma unroll
        for (int hh = 0; hh < 2; ++hh) {
            int p = mw*32 + mi*16 + hh*8 + g;
#pragma unroll
            for (int nn = 0; nn < 8; ++nn) {
                int px = nw*64 + nn*8 + q4*2;
                s_out[(size_t)px*136 + p]     = __float2half(d[mi][nn][hh*2 + 0]);
                s_out[(size_t)(px+1)*136 + p] = __float2half(d[mi][nn][hh*2 + 1]);
            }
        }
    __syncthreads();
    if (tid < 128) {
        g_ps1[tile*128 + tid] = s_sum[tid] + s_sum[128 + tid];
        g_ps2[tile*128 + tid] = s_sq[tid]  + s_sq[128 + tid];
    }
    __half* ob = actout + ((size_t)(b*PW + y + 2)*PW + 2 + xh)*128;
    for (int id = tid; id < 2048; id += 256) {
        int px = id >> 4, qc = id & 15;
        *(uint4*)(ob + (size_t)px*128 + qc*8) = *(uint4*)((char*)dsm + px*272 + qc*16);
    }
}

// ---------------- final: BN4+ReLU, max over m, 1x1 + sigmoid (conv4 raw fp16 in actA) ----------------
__global__ void final_kernel(const float* __restrict__ fw, float* __restrict__ out) {
    int gid = blockIdx.x * 256 + threadIdx.x;    // 131072
    int b = gid >> 16, pix = gid & 65535;
    int y = pix >> 8, x = pix & 255;
    const __half* p = g_actA + ((size_t)(b*PW + y + 2)*PW + x + 2)*128;
    float acc = 0.f;
#pragma unroll 1
    for (int co = 0; co < 16; ++co) {
        float sc = g_sc[co], bi = g_bi[co];
        uint4 v = *(const uint4*)(p + co*8);
        const __half* h = (const __half*)&v;
        float mv = 0.f;
#pragma unroll
        for (int m = 0; m < 8; ++m) {
            float f = fmaf(__half2float(h[m]), sc, bi);
            mv = fmaxf(mv, f);
        }
        acc = fmaf(fw[co], mv, acc);
    }
    out[gid] = 1.0f / (1.0f + expf(-acc));
}

// ---------------- launch ----------------
extern "C" void kernel_launch(void* const* d_in, const int* in_sizes, int n_in,
                              void* d_out, int out_size) {
    const float* x  = (const float*)d_in[0];
    const float* lw = (const float*)d_in[1];
    const float* w1 = (const float*)d_in[2];
    const float* w2 = (const float*)d_in[3];
    const float* w3 = (const float*)d_in[4];
    const float* w4 = (const float*)d_in[5];
    const float* fw = (const float*)d_in[6];
    const float* g0 = (const float*)d_in[7];  const float* b0 = (const float*)d_in[8];
    const float* g1 = (const float*)d_in[9];  const float* b1 = (const float*)d_in[10];
    const float* g2 = (const float*)d_in[11]; const float* b2 = (const float*)d_in[12];
    const float* g3 = (const float*)d_in[13]; const float* b3 = (const float*)d_in[14];
    const float* g4 = (const float*)d_in[15]; const float* b4 = (const float*)d_in[16];
    float* out = (float*)d_out;

    const int SMEM = 135168;   // 2 B windows (67584) + 2 W stages (65536) + sums (2048)
    cudaFuncSetAttribute(mma_conv_kernel, cudaFuncAttributeMaxDynamicSharedMemorySize, SMEM);

    // lift (raw) -> BN0 stats -> raw fp16 padded actA
    rotate_lift_kernel<<<74, 256>>>(lw);
    lift_kernel<<<dim3(16,16,16), 256>>>(x);
    stats_partial_kernel<<<dim3(64,16), 256>>>();
    stats_final_kernel<<<1, 16>>>(g0, b0);
    convert_kernel<<<dim3(9,260,2), 256>>>();

    // layer1: actA(raw, BN0 in-load) -> actB raw
    pack_g_kernel<<<1600, 256>>>(w1);
    mma_conv_kernel<<<1024, 256, SMEM>>>(0, 0);
    stats_final_mma<<<16, 256>>>(g1, b1);
    border_copy_kernel<<<dim3(129,2), 256>>>(1);

    // layer2: actB(raw, BN1 in-load) -> actA raw
    pack_g_kernel<<<1600, 256>>>(w2);
    mma_conv_kernel<<<1024, 256, SMEM>>>(1, 0);
    stats_final_mma<<<16, 256>>>(g2, b2);
    border_copy_kernel<<<dim3(129,2), 256>>>(0);

    // layer3: actA(raw, BN2 in-load) -> actB raw
    pack_g_kernel<<<1600, 256>>>(w3);
    mma_conv_kernel<<<1024, 256, SMEM>>>(0, 0);
    stats_final_mma<<<16, 256>>>(g3, b3);
    border_copy_kernel<<<dim3(129,2), 256>>>(1);

    // conv4 (1x1): actB(raw, BN3 in-load) -> actA raw; BN4 folded into final
    pack_w4_kernel<<<64, 256>>>(w4);
    mma_conv_kernel<<<1024, 256, SMEM>>>(1, 1);
    stats_final_mma<<<16, 256>>>(g4, b4);

    final_kernel<<<512, 256>>>(fw, out);
}

// round 8
// speedup vs baseline: 10.1440x; 1.1302x over previous
#include <cuda_runtime.h>
#include <cuda_fp16.h>
#include <math.h>
#include <stdint.h>

#define HW 65536
#define PW 260

// ---------------- device scratch (allocation-free) ----------------
__device__ float  g_raw[2*128*HW];                        // lift output fp32 [b][c16][m8][y][x]
__device__ __align__(1024) __half g_actA[2*PW*PW*128];    // padded NHWC fp16 RAW (ping)
__device__ __align__(1024) __half g_actB[2*PW*PW*128];    // padded NHWC fp16 RAW (pong)
__device__ __align__(1024) __half g_wA[25*16384];         // gconv weights [tap][p][q] fp16
__device__ __align__(1024) __half g_wA4[16384];           // conv4 weights [p][q] fp16
__device__ float g_wrL[8*3*16*49];
__device__ float g_psum[16*64], g_psq[16*64];
__device__ float g_ps1[1024*128], g_ps2[1024*128];        // per-tile per-p partials
__device__ float g_sc[16], g_bi[16];

// ---------------- PTX helpers (sm_80-era, portable to plain sm_103) ----------------
__device__ __forceinline__ uint32_t smem_u32(const void* p) {
    uint32_t a;
    asm("{ .reg .u64 t; cvta.to.shared.u64 t, %1; cvt.u32.u64 %0, t; }" : "=r"(a) : "l"(p));
    return a;
}
__device__ __forceinline__ void cp_async16(uint32_t s, const void* g) {
    asm volatile("cp.async.cg.shared.global [%0], [%1], 16;" :: "r"(s), "l"(g) : "memory");
}
__device__ __forceinline__ void ldm_x4(uint32_t* r, uint32_t a) {
    asm volatile("ldmatrix.sync.aligned.m8n8.x4.shared.b16 {%0,%1,%2,%3}, [%4];"
        : "=r"(r[0]), "=r"(r[1]), "=r"(r[2]), "=r"(r[3]) : "r"(a));
}
__device__ __forceinline__ void mma16816(float* d, const uint32_t* a, const uint32_t* b) {
    asm volatile("mma.sync.aligned.m16n8k16.row.col.f32.f16.f16.f32 "
        "{%0,%1,%2,%3}, {%4,%5,%6,%7}, {%8,%9}, {%0,%1,%2,%3};"
        : "+f"(d[0]), "+f"(d[1]), "+f"(d[2]), "+f"(d[3])
        : "r"(a[0]), "r"(a[1]), "r"(a[2]), "r"(a[3]), "r"(b[0]), "r"(b[1]));
}

// ---------------- bilinear kernel rotation ----------------
__device__ __forceinline__ float rot_sample(const float* W, int k, float cs, float sn, int i, int j) {
    float c  = 0.5f * (float)(k - 1);
    float ys = (float)i - c, xs = (float)j - c;
    float sy = cs * ys - sn * xs + c;
    float sx = sn * ys + cs * xs + c;
    float fy = floorf(sy), fx = floorf(sx);
    int y0 = (int)fy, x0 = (int)fx;
    float wy = sy - fy, wx = sx - fx;
    float v00 = (y0   >= 0 && y0   < k && x0   >= 0 && x0   < k) ? W[y0*k + x0]       : 0.f;
    float v01 = (y0   >= 0 && y0   < k && x0+1 >= 0 && x0+1 < k) ? W[y0*k + x0 + 1]   : 0.f;
    float v10 = (y0+1 >= 0 && y0+1 < k && x0   >= 0 && x0   < k) ? W[(y0+1)*k + x0]   : 0.f;
    float v11 = (y0+1 >= 0 && y0+1 < k && x0+1 >= 0 && x0+1 < k) ? W[(y0+1)*k + x0+1] : 0.f;
    return v00*(1.f-wy)*(1.f-wx) + v01*(1.f-wy)*wx + v10*wy*(1.f-wx) + v11*wy*wx;
}

__global__ void rotate_lift_kernel(const float* __restrict__ lw) {
    int idx = blockIdx.x * 256 + threadIdx.x;
    if (idx >= 8*3*16*49) return;
    int j  = idx % 49;
    int co = (idx / 49) % 16;
    int ci = (idx / (49*16)) % 3;
    int m  = idx / (49*48);
    float th = (float)m * 0.78539816339744831f;
    float cs = cosf(th), sn = sinf(th);
    const float* W = lw + (co*3 + ci) * 49;
    g_wrL[((m*3 + ci)*16 + co)*49 + j] = rot_sample(W, 7, cs, sn, j/7, j%7);
}

__global__ void pack_g_kernel(const float* __restrict__ w) {
    int idx = blockIdx.x * 256 + threadIdx.x;   // 409600 exact
    int tap = idx >> 14;
    int p = (idx >> 7) & 127, q = idx & 127;
    int co = p >> 3, m = p & 7, ci = q >> 3, o = q & 7;
    int oo = (o - m) & 7;
    float th = (float)m * 0.78539816339744831f;
    float cs = cosf(th), sn = sinf(th);
    float v = rot_sample(w + ((co*16 + ci)*8 + oo)*25, 5, cs, sn, tap/5, tap%5);
    g_wA[tap*16384 + p*128 + q] = __float2half(v);
}

__global__ void pack_w4_kernel(const float* __restrict__ w4) {
    int idx = blockIdx.x * 256 + threadIdx.x;   // 16384
    int p = idx >> 7, q = idx & 127;
    int co = p >> 3, m = p & 7, ci = q >> 3, o = q & 7;
    g_wA4[idx] = __float2half(w4[(co*16 + ci)*8 + ((o - m) & 7)]);
}

// ---------------- lift conv (scalar fp32) -> g_raw ----------------
__global__ __launch_bounds__(256) void lift_kernel(const float* __restrict__ x) {
    int z = blockIdx.z; int b = z >> 3, m = z & 7;
    int x0 = blockIdx.x * 16, y0 = blockIdx.y * 16;
    int t = threadIdx.x; int tx = t & 15, ty = t >> 4;
    __shared__ float s_in[22*22];
    __shared__ float s_w[16*49];
    float acc[16];
#pragma unroll
    for (int i = 0; i < 16; ++i) acc[i] = 0.f;
#pragma unroll 1
    for (int ci = 0; ci < 3; ++ci) {
        const float* ip = x + (b*3 + ci) * HW;
        for (int idx = t; idx < 484; idx += 256) {
            int iy = idx / 22, ix = idx - iy*22;
            int gy = y0 + iy - 3; gy = gy < 0 ? -gy : (gy > 255 ? 510 - gy : gy);
            int gx = x0 + ix - 3; gx = gx < 0 ? -gx : (gx > 255 ? 510 - gx : gx);
            s_in[idx] = ip[gy*256 + gx];
        }
        const float* wp = g_wrL + (m*3 + ci) * 784;
        for (int idx = t; idx < 784; idx += 256) s_w[idx] = wp[idx];
        __syncthreads();
        float tap[49];
#pragma unroll
        for (int ky = 0; ky < 7; ++ky)
#pragma unroll
            for (int kx = 0; kx < 7; ++kx)
                tap[ky*7 + kx] = s_in[(ty+ky)*22 + tx + kx];
#pragma unroll
        for (int co = 0; co < 16; ++co) {
            float a = acc[co];
#pragma unroll
            for (int j = 0; j < 49; ++j) a = fmaf(tap[j], s_w[co*49 + j], a);
            acc[co] = a;
        }
        __syncthreads();
    }
    int pix = (y0 + ty) * 256 + x0 + tx;
#pragma unroll
    for (int co = 0; co < 16; ++co)
        g_raw[((b*16 + co)*8 + m)*HW + pix] = acc[co];
}

// ---------------- BN0 stats on g_raw ----------------
__global__ void stats_partial_kernel() {
    int c = blockIdx.y, chunk = blockIdx.x, t = threadIdx.x;
    float s = 0.f, ss = 0.f;
    int base = chunk * 16384 + t;
#pragma unroll 4
    for (int k = 0; k < 64; ++k) {
        int e = base + k * 256;
        int b = e >> 19;
        int r = e & ((1 << 19) - 1);
        float v = g_raw[((b*16 + c) << 19) + r];
        s += v; ss += v * v;
    }
    __shared__ float sh1[256], sh2[256];
    sh1[t] = s; sh2[t] = ss;
    __syncthreads();
    for (int off = 128; off > 0; off >>= 1) {
        if (t < off) { sh1[t] += sh1[t + off]; sh2[t] += sh2[t + off]; }
        __syncthreads();
    }
    if (t == 0) { g_psum[c*64 + chunk] = sh1[0]; g_psq[c*64 + chunk] = sh2[0]; }
}

__global__ void stats_final_kernel(const float* __restrict__ g, const float* __restrict__ b) {
    int c = threadIdx.x;
    if (c >= 16) return;
    float s = 0.f, ss = 0.f;
    for (int i = 0; i < 64; ++i) { s += g_psum[c*64 + i]; ss += g_psq[c*64 + i]; }
    const float invN = 1.0f / 1048576.0f;
    float mean = s * invN;
    float var  = ss * invN - mean * mean;
    float sc = g[c] * rsqrtf(var + 1e-5f);
    g_sc[c] = sc;
    g_bi[c] = b[c] - mean * sc;
}

// BN stats from MMA epilogue partials (1024 tiles x 128 p)
__global__ void stats_final_mma(const float* __restrict__ g, const float* __restrict__ b) {
    int c = blockIdx.x, t = threadIdx.x;
    float s = 0.f, ss = 0.f;
    for (int e = t; e < 8192; e += 256) {
        int idx = (e >> 3) * 128 + c*8 + (e & 7);
        s += g_ps1[idx]; ss += g_ps2[idx];
    }
    __shared__ float sh1[256], sh2[256];
    sh1[t] = s; sh2[t] = ss;
    __syncthreads();
    for (int off = 128; off > 0; off >>= 1) {
        if (t < off) { sh1[t] += sh1[t + off]; sh2[t] += sh2[t + off]; }
        __syncthreads();
    }
    if (t == 0) {
        const float invN = 1.0f / 1048576.0f;
        float mean = sh1[0] * invN;
        float var  = sh2[0] * invN - mean * mean;
        float sc = g[c] * rsqrtf(var + 1e-5f);
        g_sc[c] = sc;
        g_bi[c] = b[c] - mean * sc;
    }
}

// ---------------- convert0: RAW fp32 -> padded fp16 NHWC (reflect borders) ----------------
__global__ __launch_bounds__(256) void convert_kernel() {
    __shared__ __half s[128][33];
    int t = threadIdx.x;
    int py = blockIdx.y, b = blockIdx.z;
    int pxb = blockIdx.x * 32;
    int sy = py - 2; sy = sy < 0 ? -sy : (sy > 255 ? 510 - sy : sy);
    int lanepx = t & 31, wch = t >> 5;
    {
        int pg = pxb + lanepx;
        int sx = pg - 2; sx = sx < 0 ? -sx : (sx > 255 ? 510 - sx : sx);
        bool ok = pg < PW;
        const float* rp = g_raw + (size_t)b*128*HW + sy*256 + sx;
#pragma unroll
        for (int i = 0; i < 16; ++i) {
            int ch = wch + i*8;
            float f = ok ? rp[(size_t)ch * HW] : 0.f;
            s[ch][lanepx] = __float2half(f);
        }
    }
    __syncthreads();
#pragma unroll
    for (int i = 0; i < 2; ++i) {
        int idx = i*256 + t;
        int px = idx >> 4, qc = idx & 15;
        int pg = pxb + px;
        if (pg >= PW) continue;
        __half h[8];
#pragma unroll
        for (int k = 0; k < 8; ++k) h[k] = s[qc*8 + k][px];
        *(uint4*)(g_actA + ((size_t)(b*PW + py)*PW + pg)*128 + qc*8) = *(uint4*)h;
    }
}

// ---------------- raw mirror border copy (after each mma layer) ----------------
__global__ void border_copy_kernel(int which) {   // grid (129, 2), block 256
    __half* act = which ? g_actB : g_actA;
    int gid = blockIdx.x * 256 + threadIdx.x;
    if (gid >= 2064*16) return;
    int b = blockIdx.y;
    int i = gid >> 4, qc = gid & 15;
    int py, px;
    if (i < 520)       { py = i / 260;                 px = i % 260; }
    else if (i < 1040) { int j = i - 520; py = 258 + j / 260; px = j % 260; }
    else               { int j = i - 1040; py = 2 + (j >> 2); int c = j & 3; px = (c & 1) + ((c >> 1) * 258); }
    int uy = py - 2; uy = uy < 0 ? -uy : (uy > 255 ? 510 - uy : uy);
    int ux = px - 2; ux = ux < 0 ? -ux : (ux > 255 ? 510 - ux : ux);
    uint4 v = *(uint4*)(act + ((size_t)(b*PW + uy + 2)*PW + ux + 2)*128 + qc*8);
    *(uint4*)(act + ((size_t)(b*PW + py)*PW + px)*128 + qc*8) = v;
}

// ---------------- mma.sync implicit-GEMM conv, 128px tiles, single-buffer B, occ 2 ----------------
// grid 1024; 256 thr = 8 warps (mw=w&3: 32p, nw=w>>2: 64px). Acts RAW; BN+ReLU applied
// in SMEM once per B window. SMEM: B 33792 + W 2x32768 + sums 2048 = 101376 (occ 2).
#define BSTG 33792   // 132 px x 256 B
__global__ __launch_bounds__(256, 2) void mma_conv_kernel(int dir, int is1x1) {
    extern __shared__ __align__(256) char dsm[];
    uint32_t sbase = smem_u32(dsm);
    uint32_t Wbase = sbase + BSTG;
    float* s_sum = (float*)(dsm + BSTG + 65536);   // [2][128]
    float* s_sq  = (float*)(dsm + BSTG + 65536 + 1024);

    const __half* actin = dir ? g_actB : g_actA;
    __half* actout      = dir ? g_actA : g_actB;

    int tid = threadIdx.x, w = tid >> 5, lane = tid & 31;
    int mw = w & 3, nw = w >> 2;
    int tile = blockIdx.x;
    int b = tile >> 9, rem = tile & 511;
    int y = rem >> 1, xh = (rem & 1) << 7;
    int ntap = is1x1 ? 1 : 25;
    const __half* wsrc = is1x1 ? g_wA4 : g_wA;
    const __half* actb = actin + (size_t)b * PW * PW * 128;

    float d[2][8][4];
#pragma unroll
    for (int mi = 0; mi < 2; ++mi)
#pragma unroll
        for (int nn = 0; nn < 8; ++nn)
#pragma unroll
            for (int k = 0; k < 4; ++k) d[mi][nn][k] = 0.f;

    auto load_brow = [&](int ky) {
        const __half* src = actb + ((size_t)(y + ky) * PW + xh) * 128;
        for (int id = tid; id < 2112; id += 256) {
            int r = id >> 4, c = id & 15;
            cp_async16(sbase + r*256 + ((c ^ (r & 7)) * 16), src + id*8);
        }
    };
    auto load_w = [&](int tp, int stg) {
        const __half* src = wsrc + tp * 16384;
        uint32_t Ab = Wbase + (uint32_t)stg * 32768;
#pragma unroll
        for (int it = 0; it < 8; ++it) {
            int id = it*256 + tid; int r = id >> 4, c = id & 15;
            cp_async16(Ab + r*256 + ((c ^ (r & 7)) * 16), src + id*8);
        }
    };
    auto bn_stage = [&]() {
        for (int id = tid; id < 2112; id += 256) {
            int r = id >> 4, c = id & 15;
            uint32_t ad = sbase + r*256 + ((c ^ (r & 7)) * 16);
            uint4 v; asm volatile("ld.shared.v4.b32 {%0,%1,%2,%3}, [%4];"
                : "=r"(v.x), "=r"(v.y), "=r"(v.z), "=r"(v.w) : "r"(ad));
            __half* h = (__half*)&v;
            float sc = g_sc[c], bi = g_bi[c];
#pragma unroll
            for (int k = 0; k < 8; ++k)
                h[k] = __float2half(fmaxf(fmaf(__half2float(h[k]), sc, bi), 0.f));
            asm volatile("st.shared.v4.b32 [%0], {%1,%2,%3,%4};"
                :: "r"(ad), "r"(v.x), "r"(v.y), "r"(v.z), "r"(v.w));
        }
    };

    load_brow(is1x1 ? 2 : 0);
    load_w(0, 0);
    asm volatile("cp.async.commit_group;" ::: "memory");

#pragma unroll 1
    for (int t = 0; t < ntap; ++t) {
        int kx = is1x1 ? 2 : t % 5;
        if (t + 1 < ntap) {
            load_w(t + 1, (t + 1) & 1);
            asm volatile("cp.async.commit_group;" ::: "memory");
            asm volatile("cp.async.wait_group 1;" ::: "memory");
        } else {
            asm volatile("cp.async.wait_group 0;" ::: "memory");
        }
        __syncthreads();                      // W(t) (+B window if fresh) visible
        if ((t % 5) == 0) {                   // fresh B window: BN+ReLU in smem
            bn_stage();
            __syncthreads();
        }
        uint32_t Ab = Wbase + (uint32_t)(t & 1) * 32768;
        int arb = mw*32 + (lane & 15);
        int acs = lane >> 4;
        int brb = kx + nw*64 + (lane & 7) + ((lane >> 4) << 3);
        int bcs = (lane >> 3) & 1;
#pragma unroll
        for (int ks = 0; ks < 8; ++ks) {
            uint32_t a[2][4];
#pragma unroll
            for (int mi = 0; mi < 2; ++mi) {
                int r = arb + mi*16, c = ks*2 + acs;
                ldm_x4(a[mi], Ab + r*256 + ((c ^ (r & 7)) * 16));
            }
            uint32_t bf[8][2];
#pragma unroll
            for (int nj = 0; nj < 4; ++nj) {
                int r = brb + nj*16, c = ks*2 + bcs;
                uint32_t q[4];
                ldm_x4(q, sbase + r*256 + ((c ^ (r & 7)) * 16));
                bf[nj*2][0] = q[0]; bf[nj*2][1] = q[1];
                bf[nj*2+1][0] = q[2]; bf[nj*2+1][1] = q[3];
            }
#pragma unroll
            for (int mi = 0; mi < 2; ++mi)
#pragma unroll
                for (int nn = 0; nn < 8; ++nn)
                    mma16816(d[mi][nn], a[mi], bf[nn]);
        }
        __syncthreads();                      // before B/W overwrite
        if (!is1x1 && (t + 1) % 5 == 0 && t + 1 < ntap) {
            load_brow((t + 1) / 5);           // refill single B window
            asm volatile("cp.async.commit_group;" ::: "memory");
        }
    }

    // ---- deterministic per-p sums ----
    int g = lane >> 2, q4 = lane & 3;
    float psum[4], psq[4];
#pragma unroll
    for (int i = 0; i < 4; ++i) { psum[i] = 0.f; psq[i] = 0.f; }
#pragma unroll
    for (int mi = 0; mi < 2; ++mi)
#pragma unroll
        for (int hh = 0; hh < 2; ++hh) {
            int pidx = mi*2 + hh;
#pragma unroll
            for (int nn = 0; nn < 8; ++nn) {
                float v0 = d[mi][nn][hh*2 + 0], v1 = d[mi][nn][hh*2 + 1];
                psum[pidx] += v0 + v1;
                psq[pidx]  += v0*v0 + v1*v1;
            }
        }
#pragma unroll
    for (int i = 0; i < 4; ++i) {
        psum[i] += __shfl_xor_sync(0xFFFFFFFF, psum[i], 1);
        psum[i] += __shfl_xor_sync(0xFFFFFFFF, psum[i], 2);
        psq[i]  += __shfl_xor_sync(0xFFFFFFFF, psq[i], 1);
        psq[i]  += __shfl_xor_sync(0xFFFFFFFF, psq[i], 2);
    }
    if (q4 == 0) {
#pragma unroll
        for (int mi = 0; mi < 2; ++mi)
#pragma unroll
            for (int hh = 0; hh < 2; ++hh) {
                int p = mw*32 + mi*16 + hh*8 + g;
                s_sum[nw*128 + p] = psum[mi*2 + hh];
                s_sq[nw*128 + p]  = psq[mi*2 + hh];
            }
    }
    // ---- transpose D -> raw fp16 NHWC via smem (reuse B + W0 area) ----
    __half* s_out = (__half*)dsm;                  // 128 px x 136-half stride (34816 B)
#pragma unroll
    for (int mi = 0; mi < 2; ++mi)
#pragma unroll
        for (int hh = 0; hh < 2; ++hh) {
            int p = mw*32 + mi*16 + hh*8 + g;
#pragma unroll
            for (int nn = 0; nn < 8; ++nn) {
                int px = nw*64 + nn*8 + q4*2;
                s_out[(size_t)px*136 + p]     = __float2half(d[mi][nn][hh*2 + 0]);
                s_out[(size_t)(px+1)*136 + p] = __float2half(d[mi][nn][hh*2 + 1]);
            }
        }
    __syncthreads();
    if (tid < 128) {
        g_ps1[tile*128 + tid] = s_sum[tid] + s_sum[128 + tid];
        g_ps2[tile*128 + tid] = s_sq[tid]  + s_sq[128 + tid];
    }
    __half* ob = actout + ((size_t)(b*PW + y + 2)*PW + 2 + xh)*128;
    for (int id = tid; id < 2048; id += 256) {
        int px = id >> 4, qc = id & 15;
        *(uint4*)(ob + (size_t)px*128 + qc*8) = *(uint4*)((char*)dsm + px*272 + qc*16);
    }
}

// ---------------- final: BN4+ReLU, max over m, 1x1 + sigmoid (conv4 raw fp16 in actA) ----------------
__global__ void final_kernel(const float* __restrict__ fw, float* __restrict__ out) {
    int gid = blockIdx.x * 256 + threadIdx.x;    // 131072
    int b = gid >> 16, pix = gid & 65535;
    int y = pix >> 8, x = pix & 255;
    const __half* p = g_actA + ((size_t)(b*PW + y + 2)*PW + x + 2)*128;
    float acc = 0.f;
#pragma unroll 1
    for (int co = 0; co < 16; ++co) {
        float sc = g_sc[co], bi = g_bi[co];
        uint4 v = *(const uint4*)(p + co*8);
        const __half* h = (const __half*)&v;
        float mv = 0.f;
#pragma unroll
        for (int m = 0; m < 8; ++m) {
            float f = fmaf(__half2float(h[m]), sc, bi);
            mv = fmaxf(mv, f);
        }
        acc = fmaf(fw[co], mv, acc);
    }
    out[gid] = 1.0f / (1.0f + expf(-acc));
}

// ---------------- launch ----------------
extern "C" void kernel_launch(void* const* d_in, const int* in_sizes, int n_in,
                              void* d_out, int out_size) {
    const float* x  = (const float*)d_in[0];
    const float* lw = (const float*)d_in[1];
    const float* w1 = (const float*)d_in[2];
    const float* w2 = (const float*)d_in[3];
    const float* w3 = (const float*)d_in[4];
    const float* w4 = (const float*)d_in[5];
    const float* fw = (const float*)d_in[6];
    const float* g0 = (const float*)d_in[7];  const float* b0 = (const float*)d_in[8];
    const float* g1 = (const float*)d_in[9];  const float* b1 = (const float*)d_in[10];
    const float* g2 = (const float*)d_in[11]; const float* b2 = (const float*)d_in[12];
    const float* g3 = (const float*)d_in[13]; const float* b3 = (const float*)d_in[14];
    const float* g4 = (const float*)d_in[15]; const float* b4 = (const float*)d_in[16];
    float* out = (float*)d_out;

    const int SMEM = 101376;   // B window 33792 + 2 W stages 65536 + sums 2048
    cudaFuncSetAttribute(mma_conv_kernel, cudaFuncAttributeMaxDynamicSharedMemorySize, SMEM);

    // lift (raw) -> BN0 stats -> raw fp16 padded actA
    rotate_lift_kernel<<<74, 256>>>(lw);
    lift_kernel<<<dim3(16,16,16), 256>>>(x);
    stats_partial_kernel<<<dim3(64,16), 256>>>();
    stats_final_kernel<<<1, 16>>>(g0, b0);
    convert_kernel<<<dim3(9,260,2), 256>>>();

    // layer1: actA(raw, BN0 in-load) -> actB raw
    pack_g_kernel<<<1600, 256>>>(w1);
    mma_conv_kernel<<<1024, 256, SMEM>>>(0, 0);
    stats_final_mma<<<16, 256>>>(g1, b1);
    border_copy_kernel<<<dim3(129,2), 256>>>(1);

    // layer2: actB(raw, BN1 in-load) -> actA raw
    pack_g_kernel<<<1600, 256>>>(w2);
    mma_conv_kernel<<<1024, 256, SMEM>>>(1, 0);
    stats_final_mma<<<16, 256>>>(g2, b2);
    border_copy_kernel<<<dim3(129,2), 256>>>(0);

    // layer3: actA(raw, BN2 in-load) -> actB raw
    pack_g_kernel<<<1600, 256>>>(w3);
    mma_conv_kernel<<<1024, 256, SMEM>>>(0, 0);
    stats_final_mma<<<16, 256>>>(g3, b3);
    border_copy_kernel<<<dim3(129,2), 256>>>(1);

    // conv4 (1x1): actB(raw, BN3 in-load) -> actA raw; BN4 folded into final
    pack_w4_kernel<<<64, 256>>>(w4);
    mma_conv_kernel<<<1024, 256, SMEM>>>(1, 1);
    stats_final_mma<<<16, 256>>>(g4, b4);

    final_kernel<<<512, 256>>>(fw, out);
}